// round 2
// baseline (speedup 1.0000x reference)
#include <cuda_runtime.h>
#include <cstddef>

// Problem constants: B=4, C=64, H=W=256
#define HW_ 65536

typedef unsigned long long u64;

// Scratch (no cudaMalloc allowed)
__device__ float g_h [16777216];
__device__ float g_t1[16777216];
__device__ float g_t2[16777216];
__device__ float g_mean[256];
__device__ float g_rstd[256];
__device__ float g_sum[256];     // zero-initialized; finalize re-zeroes after use
__device__ float g_sumsq[256];

// ---------- packed f32x2 helpers ----------
__device__ __forceinline__ u64 pk2(float lo, float hi) {
    u64 r;
    asm("mov.b64 %0, {%1, %2};" : "=l"(r)
        : "r"(__float_as_uint(lo)), "r"(__float_as_uint(hi)));
    return r;
}
__device__ __forceinline__ float2 upk(u64 v) {
    unsigned lo, hi;
    asm("mov.b64 {%0, %1}, %2;" : "=r"(lo), "=r"(hi) : "l"(v));
    return make_float2(__uint_as_float(lo), __uint_as_float(hi));
}
__device__ __forceinline__ u64 fma2(u64 a, u64 b, u64 c) {
    u64 d;
    asm("fma.rn.f32x2 %0, %1, %2, %3;" : "=l"(d) : "l"(a), "l"(b), "l"(c));
    return d;
}
__device__ __forceinline__ u64 mul2(u64 a, u64 b) {
    u64 d;
    asm("mul.rn.f32x2 %0, %1, %2;" : "=l"(d) : "l"(a), "l"(b));
    return d;
}

// reflect-pad index for pad=1, n=256
__device__ __forceinline__ int reflx(int i) {
    return i < 0 ? 1 : (i >= 256 ? 254 : i);
}

// ---------- 1x1 input conv ----------
__global__ void conv1x1_kernel(const float* __restrict__ x,
                               const float* __restrict__ w0,
                               const float* __restrict__ b0,
                               float* __restrict__ h)
{
    __shared__ float sw[64], sb[64];
    int tid = threadIdx.x;
    if (tid < 64) { sw[tid] = w0[tid]; sb[tid] = b0[tid]; }
    __syncthreads();
    int p = blockIdx.x * 256 + tid;
    int b = p >> 16;
    int pos = p & 65535;
    float xv = x[p];
#pragma unroll
    for (int o = 0; o < 64; ++o) {
        h[(((size_t)(b * 64 + o)) << 16) + pos] = fmaf(sw[o], xv, sb[o]);
    }
}

// ---------- finalize instance-norm stats (and re-zero accumulators) ----------
__global__ void finalize_stats_kernel(float* __restrict__ sums,
                                      float* __restrict__ sumsqs,
                                      float* __restrict__ meanv,
                                      float* __restrict__ rstdv)
{
    int bc = threadIdx.x;   // 256 threads
    float m   = sums[bc]   * (1.0f / 65536.0f);
    float var = sumsqs[bc] * (1.0f / 65536.0f) - m * m;
    meanv[bc] = m;
    rstdv[bc] = rsqrtf(var + 1e-5f);
    sums[bc]   = 0.f;       // leave zero for next accumulation
    sumsqs[bc] = 0.f;
}

// ---------- residual combine: h = relu(h + (t2-mean)*rstd), float4 ----------
__global__ void combine_kernel(float4* __restrict__ h,
                               const float4* __restrict__ t2,
                               const float* __restrict__ meanv,
                               const float* __restrict__ rstdv)
{
    size_t i = (size_t)blockIdx.x * 256 + threadIdx.x;   // 4,194,304 float4
    int bc = (int)(i >> 14);
    float m = meanv[bc], r = rstdv[bc];
    float4 t = t2[i];
    float4 hv = h[i];
    hv.x = fmaxf(hv.x + (t.x - m) * r, 0.f);
    hv.y = fmaxf(hv.y + (t.y - m) * r, 0.f);
    hv.z = fmaxf(hv.z + (t.z - m) * r, 0.f);
    hv.w = fmaxf(hv.w + (t.w - m) * r, 0.f);
    h[i] = hv;
}

// ---------- pixel-adaptive 3x3 conv ----------
// Block = one output row (b, y): 64 oc x 256 px; thread tile 8 oc x 8 px (f32x2).
// Dynamic smem layout (70848 B):
//   [0     : 9216 )  s_k  : float [9][256]
//   [9216  : 33984)  s_in : float [3][8][258]
//   [33984 : 70848)  s_w2 : u64   [4608]   layout [o][ci*9+tap]
//   s_g (guide staging) overlays s_w2.
template <bool NORM_IN, bool USE_K, bool FINAL_RELU, bool STATS>
__global__ void __launch_bounds__(256, 2)
pac_conv_kernel(const float* __restrict__ in,
                const float* __restrict__ guide,
                const float* __restrict__ w,       // [64][64][3][3]
                const float* __restrict__ bias,
                const float* __restrict__ meanv,
                const float* __restrict__ rstdv,
                float* __restrict__ out,
                float* __restrict__ sums,
                float* __restrict__ sumsqs)
{
    const int y    = blockIdx.x;
    const int b    = blockIdx.y;
    const int tid  = threadIdx.x;
    const int warp = tid >> 5;
    const int lane = tid & 31;
    const int oc_base = warp << 3;
    const int px0     = lane << 1;

    extern __shared__ __align__(16) unsigned char sraw[];
    float (*s_k)[256]     = reinterpret_cast<float(*)[256]>(sraw);
    float (*s_in)[8][258] = reinterpret_cast<float(*)[8][258]>(sraw + 9216);
    u64*  s_w2            = reinterpret_cast<u64*>(sraw + 33984);
    float (*s_g)[258]     = reinterpret_cast<float(*)[258]>(sraw + 33984);

    int yy[3];
    yy[0] = (y == 0)   ? 1   : y - 1;
    yy[1] = y;
    yy[2] = (y == 255) ? 254 : y + 1;

    if (USE_K) {
        const float* gpl = guide + ((size_t)b << 16);
        for (int idx = tid; idx < 3 * 258; idx += 256) {
            int r  = idx / 258;
            int sx = idx - r * 258;
            s_g[r][sx] = gpl[yy[r] * 256 + reflx(sx - 1)];
        }
        __syncthreads();
#pragma unroll
        for (int tap = 0; tap < 9; ++tap) {
            float d = s_g[tap / 3][tid + tap % 3] - s_g[1][tid + 1];
            s_k[tap][tid] = __expf(-0.5f * d * d);
        }
        // barrier before first s_w2 store comes from loop-top __syncthreads
    }

    u64 acc[8][4];
#pragma unroll
    for (int o = 0; o < 8; ++o)
#pragma unroll
        for (int j = 0; j < 4; ++j) acc[o][j] = 0ULL;

    const int wbase = /* c0 varies */ 0;
    (void)wbase;

    for (int cc = 0; cc < 8; ++cc) {
        const int c0 = cc << 3;
        __syncthreads();   // prior chunk compute done / s_k build done (cc=0)

        // ---- load input rows (reflect-padded; optional fused inorm+relu) ----
        for (int idx = tid; idx < 3 * 8 * 258; idx += 256) {
            int r   = idx / (8 * 258);
            int rem = idx - r * (8 * 258);
            int ci  = rem / 258;
            int sx  = rem - ci * 258;
            int c   = c0 + ci;
            float v = in[(((size_t)(b * 64 + c)) << 16) + yy[r] * 256 + reflx(sx - 1)];
            if (NORM_IN)
                v = fmaxf((v - meanv[b * 64 + c]) * rstdv[b * 64 + c], 0.f);
            s_in[r][ci][sx] = v;
        }
        // ---- stage all 9-tap weights for this chunk: contiguous LDG + STS ----
        // s_w2[idx], idx = o*72 + (ci*9 + tap);  w offset = o*576 + c0*9 + (ci*9+tap)
        {
            const float* wp = w + c0 * 9;
#pragma unroll
            for (int t = 0; t < 18; ++t) {
                int idx = t * 256 + tid;           // 18*256 = 4608
                int o   = idx / 72;
                int r   = idx - o * 72;
                float wv = wp[o * 576 + r];
                s_w2[idx] = pk2(wv, wv);
            }
        }
        __syncthreads();

#pragma unroll
        for (int ky = 0; ky < 3; ++ky) {
            u64 kk[3][4];
            if (USE_K) {
#pragma unroll
                for (int kx = 0; kx < 3; ++kx)
#pragma unroll
                    for (int j = 0; j < 4; ++j)
                        kk[kx][j] = *reinterpret_cast<const u64*>(
                            &s_k[ky * 3 + kx][(j << 6) + px0]);
            }
#pragma unroll
            for (int ci = 0; ci < 8; ++ci) {
                const float* srow = s_in[ky][ci];
                u64 vk[3][4];
#pragma unroll
                for (int j = 0; j < 4; ++j) {
                    int sx = (j << 6) + px0;
                    u64 v0 = *reinterpret_cast<const u64*>(&srow[sx]);
                    u64 v2 = *reinterpret_cast<const u64*>(&srow[sx + 2]);
                    u64 v1 = (v0 >> 32) | (v2 << 32);
                    if (USE_K) {
                        vk[0][j] = mul2(v0, kk[0][j]);
                        vk[1][j] = mul2(v1, kk[1][j]);
                        vk[2][j] = mul2(v2, kk[2][j]);
                    } else {
                        vk[0][j] = v0; vk[1][j] = v1; vk[2][j] = v2;
                    }
                }
                const u64* wr = s_w2 + oc_base * 72 + ci * 9 + ky * 3;
#pragma unroll
                for (int o = 0; o < 8; ++o) {
#pragma unroll
                    for (int kx = 0; kx < 3; ++kx) {
                        u64 w2v = wr[o * 72 + kx];   // LDS.64 broadcast
#pragma unroll
                        for (int j = 0; j < 4; ++j)
                            acc[o][j] = fma2(vk[kx][j], w2v, acc[o][j]);
                    }
                }
            }
        }
    }

    // ---- epilogue: bias (+relu), stores, optional fused IN-stats ----
#pragma unroll
    for (int o = 0; o < 8; ++o) {
        float bv = __ldg(bias + oc_base + o);
        float* op = out + (((size_t)(b * 64 + oc_base + o)) << 16) + y * 256;
        float s1 = 0.f, s2 = 0.f;
#pragma unroll
        for (int j = 0; j < 4; ++j) {
            float2 r = upk(acc[o][j]);
            r.x += bv; r.y += bv;
            if (FINAL_RELU) { r.x = fmaxf(r.x, 0.f); r.y = fmaxf(r.y, 0.f); }
            if (STATS) {
                s1 += r.x + r.y;
                s2 = fmaf(r.x, r.x, s2);
                s2 = fmaf(r.y, r.y, s2);
            }
            *reinterpret_cast<float2*>(&op[(j << 6) + px0]) = r;
        }
        if (STATS) {
#pragma unroll
            for (int off = 16; off > 0; off >>= 1) {
                s1 += __shfl_xor_sync(0xffffffffu, s1, off);
                s2 += __shfl_xor_sync(0xffffffffu, s2, off);
            }
            if (lane == 0) {
                atomicAdd(&sums  [b * 64 + oc_base + o], s1);
                atomicAdd(&sumsqs[b * 64 + oc_base + o], s2);
            }
        }
    }
}

#define PAC_SMEM 70848

// ---------- launcher ----------
extern "C" void kernel_launch(void* const* d_in, const int* in_sizes, int n_in,
                              void* d_out, int out_size)
{
    (void)in_sizes; (void)n_in; (void)out_size;
    const float* x  = (const float*)d_in[0];
    const float* w0 = (const float*)d_in[2];
    const float* b0 = (const float*)d_in[3];
    const float* wf = (const float*)d_in[4];
    const float* bf = (const float*)d_in[5];
    const float* wa[3] = {(const float*)d_in[6],  (const float*)d_in[10], (const float*)d_in[14]};
    const float* ba[3] = {(const float*)d_in[7],  (const float*)d_in[11], (const float*)d_in[15]};
    const float* wb[3] = {(const float*)d_in[8],  (const float*)d_in[12], (const float*)d_in[16]};
    const float* bb[3] = {(const float*)d_in[9],  (const float*)d_in[13], (const float*)d_in[17]};

    float *h, *t1, *t2, *mv, *rv, *sm, *sq;
    cudaGetSymbolAddress((void**)&h,  g_h);
    cudaGetSymbolAddress((void**)&t1, g_t1);
    cudaGetSymbolAddress((void**)&t2, g_t2);
    cudaGetSymbolAddress((void**)&mv, g_mean);
    cudaGetSymbolAddress((void**)&rv, g_rstd);
    cudaGetSymbolAddress((void**)&sm, g_sum);
    cudaGetSymbolAddress((void**)&sq, g_sumsq);

    static bool attr_done = false;
    if (!attr_done) {
        cudaFuncSetAttribute(pac_conv_kernel<false, true,  false, true>,
                             cudaFuncAttributeMaxDynamicSharedMemorySize, PAC_SMEM);
        cudaFuncSetAttribute(pac_conv_kernel<true,  true,  false, true>,
                             cudaFuncAttributeMaxDynamicSharedMemorySize, PAC_SMEM);
        cudaFuncSetAttribute(pac_conv_kernel<false, false, true,  false>,
                             cudaFuncAttributeMaxDynamicSharedMemorySize, PAC_SMEM);
        attr_done = true;
    }

    dim3 pg(256, 4);

    conv1x1_kernel<<<1024, 256>>>(x, w0, b0, h);

    for (int r = 0; r < 3; ++r) {
        pac_conv_kernel<false, true, false, true><<<pg, 256, PAC_SMEM>>>(
            h, x, wa[r], ba[r], nullptr, nullptr, t1, sm, sq);
        finalize_stats_kernel<<<1, 256>>>(sm, sq, mv, rv);

        pac_conv_kernel<true, true, false, true><<<pg, 256, PAC_SMEM>>>(
            t1, x, wb[r], bb[r], mv, rv, t2, sm, sq);
        finalize_stats_kernel<<<1, 256>>>(sm, sq, mv, rv);

        combine_kernel<<<16384, 256>>>((float4*)h, (const float4*)t2, mv, rv);
    }

    pac_conv_kernel<false, false, true, false><<<pg, 256, PAC_SMEM>>>(
        h, x, wf, bf, nullptr, nullptr, (float*)d_out, nullptr, nullptr);
}

// round 3
// speedup vs baseline: 1.3849x; 1.3849x over previous
#include <cuda_runtime.h>
#include <cstddef>

// Problem constants: B=4, C=64, H=W=256
#define HW_ 65536

typedef unsigned long long u64;

// Scratch (no cudaMalloc allowed)
__device__ float g_h [16777216];
__device__ float g_t1[16777216];
__device__ float g_t2[16777216];
__device__ float g_mean[256];
__device__ float g_rstd[256];
__device__ float g_sum[256];     // zero-init; finalize re-zeroes after each use
__device__ float g_sumsq[256];

// ---------- packed f32x2 helpers ----------
__device__ __forceinline__ u64 pk2(float lo, float hi) {
    u64 r;
    asm("mov.b64 %0, {%1, %2};" : "=l"(r)
        : "r"(__float_as_uint(lo)), "r"(__float_as_uint(hi)));
    return r;
}
__device__ __forceinline__ float2 upk(u64 v) {
    unsigned lo, hi;
    asm("mov.b64 {%0, %1}, %2;" : "=r"(lo), "=r"(hi) : "l"(v));
    return make_float2(__uint_as_float(lo), __uint_as_float(hi));
}
__device__ __forceinline__ u64 fma2(u64 a, u64 b, u64 c) {
    u64 d;
    asm("fma.rn.f32x2 %0, %1, %2, %3;" : "=l"(d) : "l"(a), "l"(b), "l"(c));
    return d;
}
__device__ __forceinline__ u64 mul2(u64 a, u64 b) {
    u64 d;
    asm("mul.rn.f32x2 %0, %1, %2;" : "=l"(d) : "l"(a), "l"(b));
    return d;
}

// reflect-pad index for pad=1, n=256
__device__ __forceinline__ int reflx(int i) {
    return i < 0 ? 1 : (i >= 256 ? 254 : i);
}

// ---------- 1x1 input conv ----------
__global__ void conv1x1_kernel(const float* __restrict__ x,
                               const float* __restrict__ w0,
                               const float* __restrict__ b0,
                               float* __restrict__ h)
{
    __shared__ float sw[64], sb[64];
    int tid = threadIdx.x;
    if (tid < 64) { sw[tid] = w0[tid]; sb[tid] = b0[tid]; }
    __syncthreads();
    int p = blockIdx.x * 256 + tid;
    int b = p >> 16;
    int pos = p & 65535;
    float xv = x[p];
#pragma unroll
    for (int o = 0; o < 64; ++o) {
        h[(((size_t)(b * 64 + o)) << 16) + pos] = fmaf(sw[o], xv, sb[o]);
    }
}

// ---------- finalize instance-norm stats (and re-zero accumulators) ----------
__global__ void finalize_stats_kernel(float* __restrict__ sums,
                                      float* __restrict__ sumsqs,
                                      float* __restrict__ meanv,
                                      float* __restrict__ rstdv)
{
    int bc = threadIdx.x;   // 256 threads
    float m   = sums[bc]   * (1.0f / 65536.0f);
    float var = sumsqs[bc] * (1.0f / 65536.0f) - m * m;
    meanv[bc] = m;
    rstdv[bc] = rsqrtf(var + 1e-5f);
    sums[bc]   = 0.f;
    sumsqs[bc] = 0.f;
}

// ---------- residual combine: h = relu(h + (t2-mean)*rstd), float4 ----------
__global__ void combine_kernel(float4* __restrict__ h,
                               const float4* __restrict__ t2,
                               const float* __restrict__ meanv,
                               const float* __restrict__ rstdv)
{
    size_t i = (size_t)blockIdx.x * 256 + threadIdx.x;   // 4,194,304 float4
    int bc = (int)(i >> 14);
    float m = meanv[bc], r = rstdv[bc];
    float4 t = t2[i];
    float4 hv = h[i];
    hv.x = fmaxf(hv.x + (t.x - m) * r, 0.f);
    hv.y = fmaxf(hv.y + (t.y - m) * r, 0.f);
    hv.z = fmaxf(hv.z + (t.z - m) * r, 0.f);
    hv.w = fmaxf(hv.w + (t.w - m) * r, 0.f);
    h[i] = hv;
}

// ---------- pixel-adaptive 3x3 conv ----------
// Grid (256 y, 4 b, 2 oc-half). Block = 32 oc x 256 px, 256 threads.
// Warp tile: 4 oc x 8 px (4 f32x2 pairs). Live regs ~105 -> fits 128 cap, 2 CTAs/SM.
// Dynamic smem (52416 B):
//   [0     : 9216 )  s_k  : float [9][256]
//   [9216  : 33984)  s_in : float [3][8][258]
//   [33984 : 52416)  s_w2 : u64 [2304]   layout [o_local][ci*9+tap]  (32 oc)
//   s_g (guide staging, 3096 B) overlays s_w2.
template <bool NORM_IN, bool USE_K, bool FINAL_RELU, bool STATS>
__global__ void __launch_bounds__(256, 2)
pac_conv_kernel(const float* __restrict__ in,
                const float* __restrict__ guide,
                const float* __restrict__ w,       // [64][64][3][3]
                const float* __restrict__ bias,
                const float* __restrict__ meanv,
                const float* __restrict__ rstdv,
                float* __restrict__ out,
                float* __restrict__ sums,
                float* __restrict__ sumsqs)
{
    const int y    = blockIdx.x;
    const int b    = blockIdx.y;
    const int oc_blk = blockIdx.z << 5;     // 0 or 32
    const int tid  = threadIdx.x;
    const int warp = tid >> 5;
    const int lane = tid & 31;
    const int oc_loc = warp << 2;           // local oc base (0..28)
    const int px0    = lane << 1;

    extern __shared__ __align__(16) unsigned char sraw[];
    float (*s_k)[256]     = reinterpret_cast<float(*)[256]>(sraw);
    float (*s_in)[8][258] = reinterpret_cast<float(*)[8][258]>(sraw + 9216);
    u64*  s_w2            = reinterpret_cast<u64*>(sraw + 33984);
    float (*s_g)[258]     = reinterpret_cast<float(*)[258]>(sraw + 33984);

    int yy[3];
    yy[0] = (y == 0)   ? 1   : y - 1;
    yy[1] = y;
    yy[2] = (y == 255) ? 254 : y + 1;

    if (USE_K) {
        const float* gpl = guide + ((size_t)b << 16);
        for (int idx = tid; idx < 3 * 258; idx += 256) {
            int r  = idx / 258;
            int sx = idx - r * 258;
            s_g[r][sx] = gpl[yy[r] * 256 + reflx(sx - 1)];
        }
        __syncthreads();
#pragma unroll
        for (int tap = 0; tap < 9; ++tap) {
            float d = s_g[tap / 3][tid + tap % 3] - s_g[1][tid + 1];
            s_k[tap][tid] = __expf(-0.5f * d * d);
        }
        // barrier before first s_w2 store comes from the loop-top __syncthreads
    }

    u64 acc[4][4];
#pragma unroll
    for (int o = 0; o < 4; ++o)
#pragma unroll
        for (int j = 0; j < 4; ++j) acc[o][j] = 0ULL;

    for (int cc = 0; cc < 8; ++cc) {
        const int c0 = cc << 3;
        __syncthreads();   // prior chunk compute done / s_k build done (cc=0)

        // ---- load input rows (reflect-padded; optional fused inorm+relu) ----
        for (int idx = tid; idx < 3 * 8 * 258; idx += 256) {
            int r   = idx / (8 * 258);
            int rem = idx - r * (8 * 258);
            int ci  = rem / 258;
            int sx  = rem - ci * 258;
            int c   = c0 + ci;
            float v = in[(((size_t)(b * 64 + c)) << 16) + yy[r] * 256 + reflx(sx - 1)];
            if (NORM_IN)
                v = fmaxf((v - meanv[b * 64 + c]) * rstdv[b * 64 + c], 0.f);
            s_in[r][ci][sx] = v;
        }
        // ---- stage 9-tap weights for this (chunk, 32-oc half) ----
        // s_w2[idx], idx = o*72 + (ci*9+tap); gmem = (oc_blk+o)*576 + c0*9 + r
        {
            const float* wp = w + (size_t)oc_blk * 576 + c0 * 9;
#pragma unroll
            for (int t = 0; t < 9; ++t) {
                int idx = t * 256 + tid;           // 9*256 = 2304
                int o   = idx / 72;
                int r   = idx - o * 72;
                float wv = wp[o * 576 + r];
                s_w2[idx] = pk2(wv, wv);
            }
        }
        __syncthreads();

#pragma unroll
        for (int ky = 0; ky < 3; ++ky) {
            u64 kk[3][4];
            if (USE_K) {
#pragma unroll
                for (int kx = 0; kx < 3; ++kx)
#pragma unroll
                    for (int j = 0; j < 4; ++j)
                        kk[kx][j] = *reinterpret_cast<const u64*>(
                            &s_k[ky * 3 + kx][(j << 6) + px0]);
            }
#pragma unroll
            for (int ci = 0; ci < 8; ++ci) {
                const float* srow = s_in[ky][ci];
                u64 vk[3][4];
#pragma unroll
                for (int j = 0; j < 4; ++j) {
                    int sx = (j << 6) + px0;
                    u64 v0 = *reinterpret_cast<const u64*>(&srow[sx]);
                    u64 v2 = *reinterpret_cast<const u64*>(&srow[sx + 2]);
                    u64 v1 = (v0 >> 32) | (v2 << 32);
                    if (USE_K) {
                        vk[0][j] = mul2(v0, kk[0][j]);
                        vk[1][j] = mul2(v1, kk[1][j]);
                        vk[2][j] = mul2(v2, kk[2][j]);
                    } else {
                        vk[0][j] = v0; vk[1][j] = v1; vk[2][j] = v2;
                    }
                }
                const u64* wr = s_w2 + oc_loc * 72 + ci * 9 + ky * 3;
#pragma unroll
                for (int o = 0; o < 4; ++o) {
#pragma unroll
                    for (int kx = 0; kx < 3; ++kx) {
                        u64 w2v = wr[o * 72 + kx];   // LDS.64 broadcast
#pragma unroll
                        for (int j = 0; j < 4; ++j)
                            acc[o][j] = fma2(vk[kx][j], w2v, acc[o][j]);
                    }
                }
            }
        }
    }

    // ---- epilogue: bias (+relu), stores, optional fused IN-stats ----
#pragma unroll
    for (int o = 0; o < 4; ++o) {
        const int oc = oc_blk + oc_loc + o;
        float bv = __ldg(bias + oc);
        float* op = out + (((size_t)(b * 64 + oc)) << 16) + y * 256;
        float s1 = 0.f, s2 = 0.f;
#pragma unroll
        for (int j = 0; j < 4; ++j) {
            float2 r = upk(acc[o][j]);
            r.x += bv; r.y += bv;
            if (FINAL_RELU) { r.x = fmaxf(r.x, 0.f); r.y = fmaxf(r.y, 0.f); }
            if (STATS) {
                s1 += r.x + r.y;
                s2 = fmaf(r.x, r.x, s2);
                s2 = fmaf(r.y, r.y, s2);
            }
            *reinterpret_cast<float2*>(&op[(j << 6) + px0]) = r;
        }
        if (STATS) {
#pragma unroll
            for (int off = 16; off > 0; off >>= 1) {
                s1 += __shfl_xor_sync(0xffffffffu, s1, off);
                s2 += __shfl_xor_sync(0xffffffffu, s2, off);
            }
            if (lane == 0) {
                atomicAdd(&sums  [b * 64 + oc], s1);
                atomicAdd(&sumsqs[b * 64 + oc], s2);
            }
        }
    }
}

#define PAC_SMEM 52416

// ---------- launcher ----------
extern "C" void kernel_launch(void* const* d_in, const int* in_sizes, int n_in,
                              void* d_out, int out_size)
{
    (void)in_sizes; (void)n_in; (void)out_size;
    const float* x  = (const float*)d_in[0];
    const float* w0 = (const float*)d_in[2];
    const float* b0 = (const float*)d_in[3];
    const float* wf = (const float*)d_in[4];
    const float* bf = (const float*)d_in[5];
    const float* wa[3] = {(const float*)d_in[6],  (const float*)d_in[10], (const float*)d_in[14]};
    const float* ba[3] = {(const float*)d_in[7],  (const float*)d_in[11], (const float*)d_in[15]};
    const float* wb[3] = {(const float*)d_in[8],  (const float*)d_in[12], (const float*)d_in[16]};
    const float* bb[3] = {(const float*)d_in[9],  (const float*)d_in[13], (const float*)d_in[17]};

    float *h, *t1, *t2, *mv, *rv, *sm, *sq;
    cudaGetSymbolAddress((void**)&h,  g_h);
    cudaGetSymbolAddress((void**)&t1, g_t1);
    cudaGetSymbolAddress((void**)&t2, g_t2);
    cudaGetSymbolAddress((void**)&mv, g_mean);
    cudaGetSymbolAddress((void**)&rv, g_rstd);
    cudaGetSymbolAddress((void**)&sm, g_sum);
    cudaGetSymbolAddress((void**)&sq, g_sumsq);

    cudaFuncSetAttribute(pac_conv_kernel<false, true,  false, true>,
                         cudaFuncAttributeMaxDynamicSharedMemorySize, PAC_SMEM);
    cudaFuncSetAttribute(pac_conv_kernel<true,  true,  false, true>,
                         cudaFuncAttributeMaxDynamicSharedMemorySize, PAC_SMEM);
    cudaFuncSetAttribute(pac_conv_kernel<false, false, true,  false>,
                         cudaFuncAttributeMaxDynamicSharedMemorySize, PAC_SMEM);

    dim3 pg(256, 4, 2);   // (row y, batch b, oc-half)

    conv1x1_kernel<<<1024, 256>>>(x, w0, b0, h);

    for (int r = 0; r < 3; ++r) {
        pac_conv_kernel<false, true, false, true><<<pg, 256, PAC_SMEM>>>(
            h, x, wa[r], ba[r], nullptr, nullptr, t1, sm, sq);
        finalize_stats_kernel<<<1, 256>>>(sm, sq, mv, rv);

        pac_conv_kernel<true, true, false, true><<<pg, 256, PAC_SMEM>>>(
            t1, x, wb[r], bb[r], mv, rv, t2, sm, sq);
        finalize_stats_kernel<<<1, 256>>>(sm, sq, mv, rv);

        combine_kernel<<<16384, 256>>>((float4*)h, (const float4*)t2, mv, rv);
    }

    pac_conv_kernel<false, false, true, false><<<pg, 256, PAC_SMEM>>>(
        h, x, wf, bf, nullptr, nullptr, (float*)d_out, nullptr, nullptr);
}

// round 4
// speedup vs baseline: 1.3851x; 1.0002x over previous
#include <cuda_runtime.h>
#include <cstddef>

// Problem constants: B=4, C=64, H=W=256
#define HW_ 65536

typedef unsigned long long u64;

// Scratch (no cudaMalloc allowed)
__device__ float g_h [16777216];
__device__ float g_t1[16777216];
__device__ float g_t2[16777216];
__device__ float g_mean[256];
__device__ float g_rstd[256];
__device__ float g_sum[256];     // zero-init; finalize re-zeroes after each use
__device__ float g_sumsq[256];

// ---------- packed f32x2 helpers ----------
__device__ __forceinline__ u64 pk2(float lo, float hi) {
    u64 r;
    asm("mov.b64 %0, {%1, %2};" : "=l"(r)
        : "r"(__float_as_uint(lo)), "r"(__float_as_uint(hi)));
    return r;
}
__device__ __forceinline__ float2 upk(u64 v) {
    unsigned lo, hi;
    asm("mov.b64 {%0, %1}, %2;" : "=r"(lo), "=r"(hi) : "l"(v));
    return make_float2(__uint_as_float(lo), __uint_as_float(hi));
}
__device__ __forceinline__ u64 fma2(u64 a, u64 b, u64 c) {
    u64 d;
    asm("fma.rn.f32x2 %0, %1, %2, %3;" : "=l"(d) : "l"(a), "l"(b), "l"(c));
    return d;
}
__device__ __forceinline__ u64 mul2(u64 a, u64 b) {
    u64 d;
    asm("mul.rn.f32x2 %0, %1, %2;" : "=l"(d) : "l"(a), "l"(b));
    return d;
}

// reflect-pad index for pad=1, n=256
__device__ __forceinline__ int reflx(int i) {
    return i < 0 ? 1 : (i >= 256 ? 254 : i);
}

// ---------- 1x1 input conv ----------
__global__ void conv1x1_kernel(const float* __restrict__ x,
                               const float* __restrict__ w0,
                               const float* __restrict__ b0,
                               float* __restrict__ h)
{
    __shared__ float sw[64], sb[64];
    int tid = threadIdx.x;
    if (tid < 64) { sw[tid] = w0[tid]; sb[tid] = b0[tid]; }
    __syncthreads();
    int p = blockIdx.x * 256 + tid;
    int b = p >> 16;
    int pos = p & 65535;
    float xv = x[p];
#pragma unroll
    for (int o = 0; o < 64; ++o) {
        h[(((size_t)(b * 64 + o)) << 16) + pos] = fmaf(sw[o], xv, sb[o]);
    }
}

// ---------- finalize instance-norm stats (and re-zero accumulators) ----------
__global__ void finalize_stats_kernel(float* __restrict__ sums,
                                      float* __restrict__ sumsqs,
                                      float* __restrict__ meanv,
                                      float* __restrict__ rstdv)
{
    int bc = threadIdx.x;   // 256 threads
    float m   = sums[bc]   * (1.0f / 65536.0f);
    float var = sumsqs[bc] * (1.0f / 65536.0f) - m * m;
    meanv[bc] = m;
    rstdv[bc] = rsqrtf(var + 1e-5f);
    sums[bc]   = 0.f;
    sumsqs[bc] = 0.f;
}

// ---------- residual combine: h = relu(h + (t2-mean)*rstd), float4 ----------
__global__ void combine_kernel(float4* __restrict__ h,
                               const float4* __restrict__ t2,
                               const float* __restrict__ meanv,
                               const float* __restrict__ rstdv)
{
    size_t i = (size_t)blockIdx.x * 256 + threadIdx.x;   // 4,194,304 float4
    int bc = (int)(i >> 14);
    float m = meanv[bc], r = rstdv[bc];
    float4 t = t2[i];
    float4 hv = h[i];
    hv.x = fmaxf(hv.x + (t.x - m) * r, 0.f);
    hv.y = fmaxf(hv.y + (t.y - m) * r, 0.f);
    hv.z = fmaxf(hv.z + (t.z - m) * r, 0.f);
    hv.w = fmaxf(hv.w + (t.w - m) * r, 0.f);
    h[i] = hv;
}

// ---------- pixel-adaptive 3x3 conv ----------
// Grid (256 y, 4 b, 2 oc-half). Block = 32 oc x 256 px, 256 threads.
// Warp tile: 4 oc x 8 px (4 f32x2 pairs). Live regs ~105 -> fits 128 cap, 2 CTAs/SM.
// Dynamic smem (52416 B):
//   [0     : 9216 )  s_k  : float [9][256]
//   [9216  : 33984)  s_in : float [3][8][258]
//   [33984 : 52416)  s_w2 : u64 [2304]   layout [o_local][ci*9+tap]  (32 oc)
//   s_g (guide staging, 3096 B) overlays s_w2.
template <bool NORM_IN, bool USE_K, bool FINAL_RELU, bool STATS>
__global__ void __launch_bounds__(256, 2)
pac_conv_kernel(const float* __restrict__ in,
                const float* __restrict__ guide,
                const float* __restrict__ w,       // [64][64][3][3]
                const float* __restrict__ bias,
                const float* __restrict__ meanv,
                const float* __restrict__ rstdv,
                float* __restrict__ out,
                float* __restrict__ sums,
                float* __restrict__ sumsqs)
{
    const int y    = blockIdx.x;
    const int b    = blockIdx.y;
    const int oc_blk = blockIdx.z << 5;     // 0 or 32
    const int tid  = threadIdx.x;
    const int warp = tid >> 5;
    const int lane = tid & 31;
    const int oc_loc = warp << 2;           // local oc base (0..28)
    const int px0    = lane << 1;

    extern __shared__ __align__(16) unsigned char sraw[];
    float (*s_k)[256]     = reinterpret_cast<float(*)[256]>(sraw);
    float (*s_in)[8][258] = reinterpret_cast<float(*)[8][258]>(sraw + 9216);
    u64*  s_w2            = reinterpret_cast<u64*>(sraw + 33984);
    float (*s_g)[258]     = reinterpret_cast<float(*)[258]>(sraw + 33984);

    int yy[3];
    yy[0] = (y == 0)   ? 1   : y - 1;
    yy[1] = y;
    yy[2] = (y == 255) ? 254 : y + 1;

    if (USE_K) {
        const float* gpl = guide + ((size_t)b << 16);
        for (int idx = tid; idx < 3 * 258; idx += 256) {
            int r  = idx / 258;
            int sx = idx - r * 258;
            s_g[r][sx] = gpl[yy[r] * 256 + reflx(sx - 1)];
        }
        __syncthreads();
#pragma unroll
        for (int tap = 0; tap < 9; ++tap) {
            float d = s_g[tap / 3][tid + tap % 3] - s_g[1][tid + 1];
            s_k[tap][tid] = __expf(-0.5f * d * d);
        }
        // barrier before first s_w2 store comes from the loop-top __syncthreads
    }

    u64 acc[4][4];
#pragma unroll
    for (int o = 0; o < 4; ++o)
#pragma unroll
        for (int j = 0; j < 4; ++j) acc[o][j] = 0ULL;

    for (int cc = 0; cc < 8; ++cc) {
        const int c0 = cc << 3;
        __syncthreads();   // prior chunk compute done / s_k build done (cc=0)

        // ---- load input rows (reflect-padded; optional fused inorm+relu) ----
        for (int idx = tid; idx < 3 * 8 * 258; idx += 256) {
            int r   = idx / (8 * 258);
            int rem = idx - r * (8 * 258);
            int ci  = rem / 258;
            int sx  = rem - ci * 258;
            int c   = c0 + ci;
            float v = in[(((size_t)(b * 64 + c)) << 16) + yy[r] * 256 + reflx(sx - 1)];
            if (NORM_IN)
                v = fmaxf((v - meanv[b * 64 + c]) * rstdv[b * 64 + c], 0.f);
            s_in[r][ci][sx] = v;
        }
        // ---- stage 9-tap weights for this (chunk, 32-oc half) ----
        // s_w2[idx], idx = o*72 + (ci*9+tap); gmem = (oc_blk+o)*576 + c0*9 + r
        {
            const float* wp = w + (size_t)oc_blk * 576 + c0 * 9;
#pragma unroll
            for (int t = 0; t < 9; ++t) {
                int idx = t * 256 + tid;           // 9*256 = 2304
                int o   = idx / 72;
                int r   = idx - o * 72;
                float wv = wp[o * 576 + r];
                s_w2[idx] = pk2(wv, wv);
            }
        }
        __syncthreads();

#pragma unroll
        for (int ky = 0; ky < 3; ++ky) {
            u64 kk[3][4];
            if (USE_K) {
#pragma unroll
                for (int kx = 0; kx < 3; ++kx)
#pragma unroll
                    for (int j = 0; j < 4; ++j)
                        kk[kx][j] = *reinterpret_cast<const u64*>(
                            &s_k[ky * 3 + kx][(j << 6) + px0]);
            }
#pragma unroll
            for (int ci = 0; ci < 8; ++ci) {
                const float* srow = s_in[ky][ci];
                u64 vk[3][4];
#pragma unroll
                for (int j = 0; j < 4; ++j) {
                    int sx = (j << 6) + px0;
                    u64 v0 = *reinterpret_cast<const u64*>(&srow[sx]);
                    u64 v2 = *reinterpret_cast<const u64*>(&srow[sx + 2]);
                    u64 v1 = (v0 >> 32) | (v2 << 32);
                    if (USE_K) {
                        vk[0][j] = mul2(v0, kk[0][j]);
                        vk[1][j] = mul2(v1, kk[1][j]);
                        vk[2][j] = mul2(v2, kk[2][j]);
                    } else {
                        vk[0][j] = v0; vk[1][j] = v1; vk[2][j] = v2;
                    }
                }
                const u64* wr = s_w2 + oc_loc * 72 + ci * 9 + ky * 3;
#pragma unroll
                for (int o = 0; o < 4; ++o) {
#pragma unroll
                    for (int kx = 0; kx < 3; ++kx) {
                        u64 w2v = wr[o * 72 + kx];   // LDS.64 broadcast
#pragma unroll
                        for (int j = 0; j < 4; ++j)
                            acc[o][j] = fma2(vk[kx][j], w2v, acc[o][j]);
                    }
                }
            }
        }
    }

    // ---- epilogue: bias (+relu), stores, optional fused IN-stats ----
#pragma unroll
    for (int o = 0; o < 4; ++o) {
        const int oc = oc_blk + oc_loc + o;
        float bv = __ldg(bias + oc);
        float* op = out + (((size_t)(b * 64 + oc)) << 16) + y * 256;
        float s1 = 0.f, s2 = 0.f;
#pragma unroll
        for (int j = 0; j < 4; ++j) {
            float2 r = upk(acc[o][j]);
            r.x += bv; r.y += bv;
            if (FINAL_RELU) { r.x = fmaxf(r.x, 0.f); r.y = fmaxf(r.y, 0.f); }
            if (STATS) {
                s1 += r.x + r.y;
                s2 = fmaf(r.x, r.x, s2);
                s2 = fmaf(r.y, r.y, s2);
            }
            *reinterpret_cast<float2*>(&op[(j << 6) + px0]) = r;
        }
        if (STATS) {
#pragma unroll
            for (int off = 16; off > 0; off >>= 1) {
                s1 += __shfl_xor_sync(0xffffffffu, s1, off);
                s2 += __shfl_xor_sync(0xffffffffu, s2, off);
            }
            if (lane == 0) {
                atomicAdd(&sums  [b * 64 + oc], s1);
                atomicAdd(&sumsqs[b * 64 + oc], s2);
            }
        }
    }
}

#define PAC_SMEM 52416

// ---------- launcher ----------
extern "C" void kernel_launch(void* const* d_in, const int* in_sizes, int n_in,
                              void* d_out, int out_size)
{
    (void)in_sizes; (void)n_in; (void)out_size;
    const float* x  = (const float*)d_in[0];
    const float* w0 = (const float*)d_in[2];
    const float* b0 = (const float*)d_in[3];
    const float* wf = (const float*)d_in[4];
    const float* bf = (const float*)d_in[5];
    const float* wa[3] = {(const float*)d_in[6],  (const float*)d_in[10], (const float*)d_in[14]};
    const float* ba[3] = {(const float*)d_in[7],  (const float*)d_in[11], (const float*)d_in[15]};
    const float* wb[3] = {(const float*)d_in[8],  (const float*)d_in[12], (const float*)d_in[16]};
    const float* bb[3] = {(const float*)d_in[9],  (const float*)d_in[13], (const float*)d_in[17]};

    float *h, *t1, *t2, *mv, *rv, *sm, *sq;
    cudaGetSymbolAddress((void**)&h,  g_h);
    cudaGetSymbolAddress((void**)&t1, g_t1);
    cudaGetSymbolAddress((void**)&t2, g_t2);
    cudaGetSymbolAddress((void**)&mv, g_mean);
    cudaGetSymbolAddress((void**)&rv, g_rstd);
    cudaGetSymbolAddress((void**)&sm, g_sum);
    cudaGetSymbolAddress((void**)&sq, g_sumsq);

    cudaFuncSetAttribute(pac_conv_kernel<false, true,  false, true>,
                         cudaFuncAttributeMaxDynamicSharedMemorySize, PAC_SMEM);
    cudaFuncSetAttribute(pac_conv_kernel<true,  true,  false, true>,
                         cudaFuncAttributeMaxDynamicSharedMemorySize, PAC_SMEM);
    cudaFuncSetAttribute(pac_conv_kernel<false, false, true,  false>,
                         cudaFuncAttributeMaxDynamicSharedMemorySize, PAC_SMEM);

    dim3 pg(256, 4, 2);   // (row y, batch b, oc-half)

    conv1x1_kernel<<<1024, 256>>>(x, w0, b0, h);

    for (int r = 0; r < 3; ++r) {
        pac_conv_kernel<false, true, false, true><<<pg, 256, PAC_SMEM>>>(
            h, x, wa[r], ba[r], nullptr, nullptr, t1, sm, sq);
        finalize_stats_kernel<<<1, 256>>>(sm, sq, mv, rv);

        pac_conv_kernel<true, true, false, true><<<pg, 256, PAC_SMEM>>>(
            t1, x, wb[r], bb[r], mv, rv, t2, sm, sq);
        finalize_stats_kernel<<<1, 256>>>(sm, sq, mv, rv);

        combine_kernel<<<16384, 256>>>((float4*)h, (const float4*)t2, mv, rv);
    }

    pac_conv_kernel<false, false, true, false><<<pg, 256, PAC_SMEM>>>(
        h, x, wf, bf, nullptr, nullptr, (float*)d_out, nullptr, nullptr);
}

// round 6
// speedup vs baseline: 2.3550x; 1.7002x over previous
#include <cuda_runtime.h>
#include <cuda_bf16.h>
#include <cstdint>
#include <cstddef>

typedef unsigned long long u64;
typedef unsigned int u32;

// ---------------- device scratch (no cudaMalloc allowed) ----------------
// NHWC feature buffers [b][y][x][c], 4*256*256*64 floats each
__device__ float g_h [16777216];
__device__ float g_t1[16777216];
__device__ float g_t2[16777216];
__device__ __align__(16) float g_mean[256];
__device__ __align__(16) float g_rstd[256];
__device__ __align__(16) float g_sum[256];     // zero-init; finalize re-zeroes
__device__ __align__(16) float g_sumsq[256];

// ---------------- helpers ----------------
__device__ __forceinline__ u32 smem_u32(const void* p) {
    u32 a;
    asm("{ .reg .u64 t; cvta.to.shared.u64 t, %1; cvt.u32.u64 %0, t; }"
        : "=r"(a) : "l"(p));
    return a;
}
__device__ __forceinline__ u32 swz(u32 off) { return off ^ ((off >> 3) & 0x70); }
__device__ __forceinline__ int reflx(int i) { return i < 0 ? 1 : (i >= 256 ? 254 : i); }

__device__ __forceinline__ void ldsm4(u32* r, u32 addr) {
    asm volatile("ldmatrix.sync.aligned.m8n8.x4.shared.b16 {%0,%1,%2,%3}, [%4];"
        : "=r"(r[0]), "=r"(r[1]), "=r"(r[2]), "=r"(r[3]) : "r"(addr));
}
__device__ __forceinline__ void mma16816(float* d, const u32* a, const u32* b) {
    asm volatile(
        "mma.sync.aligned.m16n8k16.row.col.f32.bf16.bf16.f32 "
        "{%0,%1,%2,%3}, {%4,%5,%6,%7}, {%8,%9}, {%0,%1,%2,%3};"
        : "+f"(d[0]), "+f"(d[1]), "+f"(d[2]), "+f"(d[3])
        : "r"(a[0]), "r"(a[1]), "r"(a[2]), "r"(a[3]), "r"(b[0]), "r"(b[1]));
}

// ---------------- smem layout (relative to 1024-aligned base) ----------------
// [0    : 256  )  bias (64 f32)
// [512  : 5120 )  s_k  float [9][128]
// [8192 : 155648) W tiles: [tap][hi/lo][64 oc][128B row], swizzled  (9*16384)
// [155648 : 189440) A tiles (hi 16K + lo 16K) / epilogue f32 [128][66] / guide staging
#define BIAS_OFF  0
#define K_OFF     512
#define W_OFF     8192
#define A_OFF     155648
#define EPI_WORDS 66
#define DSMEM     (189440 + 1024)

// =======================================================================
// PAC conv via mma.sync (bf16 hi/lo, fp32 accum). Persistent, 256 thr.
// in NHWC; out NHWC (FINAL: NCHW + relu). guide = x flat [b][y][x].
// =======================================================================
template <bool NORM_IN, bool USE_K, bool FINAL>
__global__ void __launch_bounds__(256, 1)
pac_mma_kernel(const float* __restrict__ in,
               const float* __restrict__ guide,
               const float* __restrict__ w,      // [64][64][3][3] fp32
               const float* __restrict__ bias,
               const float* __restrict__ meanv,
               const float* __restrict__ rstdv,
               float* __restrict__ out)
{
    extern __shared__ __align__(16) unsigned char dyn[];
    u32 raw0  = smem_u32(dyn);
    u32 smem0 = (raw0 + 1023) & ~1023u;
    unsigned char* sb = dyn + (smem0 - raw0);

    const int tid  = threadIdx.x;
    const int warp = tid >> 5;
    const int lane = tid & 31;
    const int wm = warp >> 1;          // 0..3 : 32-px group
    const int wn = warp & 1;           // 0..1 : 32-oc group

    // ---- one-time: weights (hi/lo, swizzled rows) + bias ----
    for (int i = tid; i < 36864; i += 256) {
        int oc  = i / 576;
        int r   = i - oc * 576;
        int c   = r / 9;
        int tap = r - c * 9;
        float wv = w[i];
        __nv_bfloat16 hb = __float2bfloat16(wv);
        __nv_bfloat16 lb = __float2bfloat16(wv - __bfloat162float(hb));
        u32 off = swz((u32)(oc * 128 + c * 2));
        *(__nv_bfloat16*)(sb + W_OFF + tap * 16384 +        off) = hb;
        *(__nv_bfloat16*)(sb + W_OFF + tap * 16384 + 8192 + off) = lb;
    }
    if (tid < 64) *(float*)(sb + BIAS_OFF + tid * 4) = bias[tid];
    __syncthreads();

    float2 nm = make_float2(0.f, 0.f), nr = make_float2(1.f, 1.f);
    int cur_b = -1;

    const u32 aHi = smem0 + A_OFF;
    const u32 aLo = smem0 + A_OFF + 16384;

    for (int tile = blockIdx.x; tile < 2048; tile += gridDim.x) {
        const int b   = tile >> 9;
        const int rem = tile & 511;
        const int y   = rem >> 1;
        const int x0  = (rem & 1) << 7;
        int yy[3];
        yy[0] = (y == 0) ? 1 : y - 1;
        yy[1] = y;
        yy[2] = (y == 255) ? 254 : y + 1;

        if (NORM_IN && b != cur_b) {
            nm = *(const float2*)(meanv + b * 64 + 2 * lane);
            nr = *(const float2*)(rstdv + b * 64 + 2 * lane);
            cur_b = b;
        }

        __syncthreads();   // prev tile epilogue reads finished; A/EPI free

        if (USE_K) {
            float* sg = (float*)(sb + A_OFF);      // [3][132] staging
            const float* gp = guide + ((size_t)b << 16);
            for (int i = tid; i < 390; i += 256) {
                int ry = i / 130, j = i - ry * 130;
                sg[ry * 132 + j] = gp[yy[ry] * 256 + reflx(x0 - 1 + j)];
            }
            __syncthreads();
            float* sk = (float*)(sb + K_OFF);
            for (int i = tid; i < 1152; i += 256) {
                int t9 = i >> 7, px = i & 127;
                float d = sg[(t9 / 3) * 132 + px + (t9 % 3)] - sg[132 + px + 1];
                sk[i] = __expf(-0.5f * d * d);
            }
            __syncthreads();
        }

        float acc[2][4][4];
#pragma unroll
        for (int mi = 0; mi < 2; ++mi)
#pragma unroll
            for (int ni = 0; ni < 4; ++ni)
#pragma unroll
                for (int q = 0; q < 4; ++q) acc[mi][ni][q] = 0.f;

        for (int t9 = 0; t9 < 9; ++t9) {
            // ---- build A (hi/lo) for this tap ----
            const int ysrc = yy[t9 / 3];
            const int dx   = (t9 % 3) - 1;
            const float* kk = (const float*)(sb + K_OFF) + t9 * 128;
            const float* rowbase =
                in + ((((size_t)b * 256 + ysrc) * 256) << 6) + 2 * lane;
#pragma unroll 4
            for (int r = warp; r < 128; r += 8) {
                int xsrc = x0 + r + dx;
                xsrc = xsrc < 0 ? 1 : (xsrc > 255 ? 254 : xsrc);
                float2 v = *(const float2*)(rowbase + ((size_t)xsrc << 6));
                float p0 = v.x, p1 = v.y;
                if (NORM_IN) {
                    p0 = fmaxf((p0 - nm.x) * nr.x, 0.f);
                    p1 = fmaxf((p1 - nm.y) * nr.y, 0.f);
                }
                if (USE_K) { float s = kk[r]; p0 *= s; p1 *= s; }
                __nv_bfloat162 h2 = __float22bfloat162_rn(make_float2(p0, p1));
                float l0 = p0 - __bfloat162float(h2.x);
                float l1 = p1 - __bfloat162float(h2.y);
                __nv_bfloat162 lo2 = __float22bfloat162_rn(make_float2(l0, l1));
                u32 off = swz((u32)(r * 128 + lane * 4));
                *(u32*)(sb + A_OFF +         off) = *(u32*)&h2;
                *(u32*)(sb + A_OFF + 16384 + off) = *(u32*)&lo2;
            }
            __syncthreads();

            // ---- 3 passes: Ahi*Whi, Alo*Whi, Ahi*Wlo ----
            const u32 wHi = smem0 + W_OFF + t9 * 16384;
            const u32 wLo = wHi + 8192;
            const u32 aRowOff = (u32)((wm * 32 + (lane & 15)) * 128 + (lane >> 4) * 16);
            const u32 bRowOff = (u32)((wn * 32 + ((lane >> 4) << 3) + (lane & 7)) * 128
                                      + ((lane >> 3) & 1) * 16);
#pragma unroll
            for (int pass = 0; pass < 3; ++pass) {
                const u32 Ab = (pass == 1) ? aLo : aHi;
                const u32 Wb = (pass == 2) ? wLo : wHi;
#pragma unroll
                for (int ks = 0; ks < 4; ++ks) {
                    u32 af[2][4], bfr[2][4];
#pragma unroll
                    for (int mi = 0; mi < 2; ++mi)
                        ldsm4(af[mi], Ab + swz(aRowOff + mi * 16 * 128 + ks * 32));
#pragma unroll
                    for (int p = 0; p < 2; ++p)
                        ldsm4(bfr[p], Wb + swz(bRowOff + p * 16 * 128 + ks * 32));
#pragma unroll
                    for (int mi = 0; mi < 2; ++mi)
#pragma unroll
                        for (int ni = 0; ni < 4; ++ni)
                            mma16816(acc[mi][ni], af[mi], &bfr[ni >> 1][(ni & 1) * 2]);
                }
            }
            __syncthreads();   // all warps done reading A before next build
        }

        // ---- epilogue: frags -> smem [128][66] -> coalesced gmem ----
        float* epi = (float*)(sb + A_OFF);
        {
            const int row = lane >> 2;
            const int cp  = (lane & 3) * 2;
#pragma unroll
            for (int mi = 0; mi < 2; ++mi)
#pragma unroll
                for (int ni = 0; ni < 4; ++ni) {
                    int px = wm * 32 + mi * 16 + row;
                    int oc = wn * 32 + ni * 8 + cp;
                    *(float2*)&epi[px * EPI_WORDS + oc] =
                        make_float2(acc[mi][ni][0], acc[mi][ni][1]);
                    *(float2*)&epi[(px + 8) * EPI_WORDS + oc] =
                        make_float2(acc[mi][ni][2], acc[mi][ni][3]);
                }
        }
        __syncthreads();

        if (FINAL) {
            // NCHW + bias + relu, coalesced along px
            for (int i = tid; i < 8192; i += 256) {
                int oc = i >> 7, px = i & 127;
                float bv = *(const float*)(sb + BIAS_OFF + oc * 4);
                float v = fmaxf(epi[px * EPI_WORDS + oc] + bv, 0.f);
                out[((size_t)(b * 64 + oc) << 16) + y * 256 + x0 + px] = v;
            }
        } else {
            // NHWC + bias, float4
            for (int i = tid; i < 2048; i += 256) {
                int px = i >> 4, c0 = (i & 15) * 4;
                float4 b4 = *(const float4*)(sb + BIAS_OFF + c0 * 4);
                float4 v;
                v.x = epi[px * EPI_WORDS + c0 + 0] + b4.x;
                v.y = epi[px * EPI_WORDS + c0 + 1] + b4.y;
                v.z = epi[px * EPI_WORDS + c0 + 2] + b4.z;
                v.w = epi[px * EPI_WORDS + c0 + 3] + b4.w;
                *(float4*)(out + ((((size_t)b * 256 + y) * 256 + x0 + px) << 6) + c0) = v;
            }
        }
    }
}

// =======================================================================
// Aux kernels (NHWC)
// =======================================================================
__global__ void conv1x1_kernel(const float* __restrict__ x,
                               const float* __restrict__ w0,
                               const float* __restrict__ b0,
                               float* __restrict__ h)   // NHWC out
{
    __shared__ float sw[64], sbv[64];
    int tid = threadIdx.x;
    if (tid < 64) { sw[tid] = w0[tid]; sbv[tid] = b0[tid]; }
    __syncthreads();
    int b = blockIdx.x >> 8, y = blockIdx.x & 255;
    const float* xr = x + ((size_t)b << 16) + y * 256;
    float* ob = h + ((((size_t)b * 256 + y) * 256) << 6);
    int c = tid & 63;
    float wv = sw[c], bv = sbv[c];
    for (int i = 0; i < 64; ++i) {
        int px = i * 4 + (tid >> 6);
        ob[((size_t)px << 6) + c] = fmaf(wv, xr[px], bv);
    }
}

__global__ void stats_kernel(const float* __restrict__ src,   // NHWC
                             float* __restrict__ sums,
                             float* __restrict__ sumsqs)
{
    int b = blockIdx.x >> 8, y = blockIdx.x & 255;
    const float* base = src + ((((size_t)b * 256 + y) * 256) << 6);
    int tid = threadIdx.x;
    int c = tid & 63, pg = tid >> 6;
    float s = 0.f, q = 0.f;
    for (int px = pg; px < 256; px += 4) {
        float v = base[((size_t)px << 6) + c];
        s += v;
        q = fmaf(v, v, q);
    }
    __shared__ float ss[256], sq[256];
    ss[tid] = s; sq[tid] = q;
    __syncthreads();
    if (tid < 128) { ss[tid] += ss[tid + 128]; sq[tid] += sq[tid + 128]; }
    __syncthreads();
    if (tid < 64) {
        atomicAdd(&sums[b * 64 + tid],   ss[tid] + ss[tid + 64]);
        atomicAdd(&sumsqs[b * 64 + tid], sq[tid] + sq[tid + 64]);
    }
}

__global__ void finalize_stats_kernel(float* __restrict__ sums,
                                      float* __restrict__ sumsqs,
                                      float* __restrict__ meanv,
                                      float* __restrict__ rstdv)
{
    int bc = threadIdx.x;
    float m   = sums[bc]   * (1.0f / 65536.0f);
    float var = sumsqs[bc] * (1.0f / 65536.0f) - m * m;
    meanv[bc] = m;
    rstdv[bc] = rsqrtf(var + 1e-5f);
    sums[bc] = 0.f;
    sumsqs[bc] = 0.f;
}

__global__ void combine_kernel(float4* __restrict__ h,         // NHWC
                               const float4* __restrict__ t2,
                               const float* __restrict__ meanv,
                               const float* __restrict__ rstdv)
{
    size_t i = (size_t)blockIdx.x * 256 + threadIdx.x;   // 4,194,304 float4
    int c4 = (int)(i & 15);
    int b  = (int)(i >> 20);
    float4 m4 = ((const float4*)meanv)[(b << 4) + c4];
    float4 r4 = ((const float4*)rstdv)[(b << 4) + c4];
    float4 t = t2[i];
    float4 hv = h[i];
    hv.x = fmaxf(hv.x + (t.x - m4.x) * r4.x, 0.f);
    hv.y = fmaxf(hv.y + (t.y - m4.y) * r4.y, 0.f);
    hv.z = fmaxf(hv.z + (t.z - m4.z) * r4.z, 0.f);
    hv.w = fmaxf(hv.w + (t.w - m4.w) * r4.w, 0.f);
    h[i] = hv;
}

// =======================================================================
// launcher
// =======================================================================
extern "C" void kernel_launch(void* const* d_in, const int* in_sizes, int n_in,
                              void* d_out, int out_size)
{
    (void)in_sizes; (void)n_in; (void)out_size;
    const float* x  = (const float*)d_in[0];
    const float* w0 = (const float*)d_in[2];
    const float* b0 = (const float*)d_in[3];
    const float* wf = (const float*)d_in[4];
    const float* bf = (const float*)d_in[5];
    const float* wa[3] = {(const float*)d_in[6],  (const float*)d_in[10], (const float*)d_in[14]};
    const float* ba[3] = {(const float*)d_in[7],  (const float*)d_in[11], (const float*)d_in[15]};
    const float* wb[3] = {(const float*)d_in[8],  (const float*)d_in[12], (const float*)d_in[16]};
    const float* bb[3] = {(const float*)d_in[9],  (const float*)d_in[13], (const float*)d_in[17]};

    float *h, *t1, *t2, *mv, *rv, *sm, *sq;
    cudaGetSymbolAddress((void**)&h,  g_h);
    cudaGetSymbolAddress((void**)&t1, g_t1);
    cudaGetSymbolAddress((void**)&t2, g_t2);
    cudaGetSymbolAddress((void**)&mv, g_mean);
    cudaGetSymbolAddress((void**)&rv, g_rstd);
    cudaGetSymbolAddress((void**)&sm, g_sum);
    cudaGetSymbolAddress((void**)&sq, g_sumsq);

    cudaFuncSetAttribute(pac_mma_kernel<false, true,  false>,
                         cudaFuncAttributeMaxDynamicSharedMemorySize, DSMEM);
    cudaFuncSetAttribute(pac_mma_kernel<true,  true,  false>,
                         cudaFuncAttributeMaxDynamicSharedMemorySize, DSMEM);
    cudaFuncSetAttribute(pac_mma_kernel<false, false, true>,
                         cudaFuncAttributeMaxDynamicSharedMemorySize, DSMEM);

    conv1x1_kernel<<<1024, 256>>>(x, w0, b0, h);

    for (int r = 0; r < 3; ++r) {
        pac_mma_kernel<false, true, false><<<148, 256, DSMEM>>>(
            h, x, wa[r], ba[r], nullptr, nullptr, t1);
        stats_kernel<<<1024, 256>>>(t1, sm, sq);
        finalize_stats_kernel<<<1, 256>>>(sm, sq, mv, rv);

        pac_mma_kernel<true, true, false><<<148, 256, DSMEM>>>(
            t1, x, wb[r], bb[r], mv, rv, t2);
        stats_kernel<<<1024, 256>>>(t2, sm, sq);
        finalize_stats_kernel<<<1, 256>>>(sm, sq, mv, rv);

        combine_kernel<<<16384, 256>>>((float4*)h, (const float4*)t2, mv, rv);
    }

    pac_mma_kernel<false, false, true><<<148, 256, DSMEM>>>(
        h, x, wf, bf, nullptr, nullptr, (float*)d_out);
}

// round 7
// speedup vs baseline: 3.2366x; 1.3744x over previous
#include <cuda_runtime.h>
#include <cuda_bf16.h>
#include <cstdint>
#include <cstddef>

typedef unsigned long long u64;
typedef unsigned int u32;

// ---------------- device scratch (no cudaMalloc allowed) ----------------
// NHWC feature buffers [b][y][x][c], 4*256*256*64 floats each
__device__ float g_h [16777216];
__device__ float g_t1[16777216];
__device__ float g_t2[16777216];
__device__ __align__(16) float g_mean[256];
__device__ __align__(16) float g_rstd[256];
__device__ __align__(16) float g_sum[256];     // zero-init; finalize re-zeroes
__device__ __align__(16) float g_sumsq[256];

// ---------------- helpers ----------------
__device__ __forceinline__ u32 smem_u32(const void* p) {
    u32 a;
    asm("{ .reg .u64 t; cvta.to.shared.u64 t, %1; cvt.u32.u64 %0, t; }"
        : "=r"(a) : "l"(p));
    return a;
}
__device__ __forceinline__ u32 swz(u32 off) { return off ^ ((off >> 3) & 0x70); }
__device__ __forceinline__ int reflx(int i) { return i < 0 ? 1 : (i >= 256 ? 254 : i); }

__device__ __forceinline__ void ldsm4(u32* r, u32 addr) {
    asm volatile("ldmatrix.sync.aligned.m8n8.x4.shared.b16 {%0,%1,%2,%3}, [%4];"
        : "=r"(r[0]), "=r"(r[1]), "=r"(r[2]), "=r"(r[3]) : "r"(addr));
}
__device__ __forceinline__ void mma16816(float* d, const u32* a, const u32* b) {
    asm volatile(
        "mma.sync.aligned.m16n8k16.row.col.f32.bf16.bf16.f32 "
        "{%0,%1,%2,%3}, {%4,%5,%6,%7}, {%8,%9}, {%0,%1,%2,%3};"
        : "+f"(d[0]), "+f"(d[1]), "+f"(d[2]), "+f"(d[3])
        : "r"(a[0]), "r"(a[1]), "r"(a[2]), "r"(a[3]), "r"(b[0]), "r"(b[1]));
}
#define GBAR(id) asm volatile("bar.sync %0, 256;" :: "r"(id) : "memory")

// ---------------- smem layout (relative to 1024-aligned base) ----------------
// [0     : 256   ) bias (64 f32)
// [512   : 9728  ) s_k  float [2 groups][9][128]
// [10240 : 157696) W tiles: [tap][hi/lo][64 oc][128B row], swizzled (9*16384)
// [157696: 223232) A tiles per group: hi 16K + lo 16K  (guide staging / FINAL epi overlay)
#define BIAS_OFF  0
#define K_OFF     512
#define W_OFF     10240
#define A_OFF     157696
#define DSMEM     (223232 + 1024)

// =======================================================================
// PAC conv via mma.sync (bf16 hi/lo, fp32 accum). Persistent, 512 thr,
// two independent 8-warp tile groups per CTA (named barriers).
// in NHWC; out NHWC + fused stats (FINAL: NCHW + relu, no stats).
// =======================================================================
template <bool NORM_IN, bool USE_K, bool FINAL>
__global__ void __launch_bounds__(512, 1)
pac_mma_kernel(const float* __restrict__ in,
               const float* __restrict__ guide,
               const float* __restrict__ w,      // [64][64][3][3] fp32
               const float* __restrict__ bias,
               const float* __restrict__ meanv,
               const float* __restrict__ rstdv,
               float* __restrict__ out,
               float* __restrict__ sums,
               float* __restrict__ sumsqs)
{
    extern __shared__ __align__(16) unsigned char dyn[];
    u32 raw0  = smem_u32(dyn);
    u32 smem0 = (raw0 + 1023) & ~1023u;
    unsigned char* sb = dyn + (smem0 - raw0);

    const int tid  = threadIdx.x;
    const int warp = tid >> 5;
    const int lane = tid & 31;
    const int g    = warp >> 3;        // tile group 0/1
    const int wg   = warp & 7;         // warp within group
    const int tg   = wg * 32 + lane;   // thread within group (0..255)
    const int wm   = wg >> 1;          // 0..3 : 32-px group
    const int wn   = wg & 1;           // 0..1 : 32-oc group
    const int barid = 1 + g;

    // ---- one-time: weights (hi/lo, swizzled rows) + bias ----
    for (int i = tid; i < 36864; i += 512) {
        int oc  = i / 576;
        int r   = i - oc * 576;
        int c   = r / 9;
        int tap = r - c * 9;
        float wv = w[i];
        __nv_bfloat16 hb = __float2bfloat16(wv);
        __nv_bfloat16 lb = __float2bfloat16(wv - __bfloat162float(hb));
        u32 off = swz((u32)(oc * 128 + c * 2));
        *(__nv_bfloat16*)(sb + W_OFF + tap * 16384 +        off) = hb;
        *(__nv_bfloat16*)(sb + W_OFF + tap * 16384 + 8192 + off) = lb;
    }
    if (tid < 64) *(float*)(sb + BIAS_OFF + tid * 4) = bias[tid];
    __syncthreads();

    // per-thread bias for fragment oc positions
    const int cp = (lane & 3) * 2;
    float2 biasv[4];
#pragma unroll
    for (int ni = 0; ni < 4; ++ni)
        biasv[ni] = *(const float2*)(bias + wn * 32 + ni * 8 + cp);

    float2 nm = make_float2(0.f, 0.f), nr = make_float2(1.f, 1.f);
    int cur_b = -1;

    const u32 aHi = smem0 + A_OFF + g * 32768;
    const u32 aLo = aHi + 16384;
    float* sk = (float*)(sb + K_OFF + g * 4608);

    for (int tile = blockIdx.x * 2 + g; tile < 2048; tile += gridDim.x * 2) {
        const int b   = tile >> 9;
        const int rem = tile & 511;
        const int y   = rem >> 1;
        const int x0  = (rem & 1) << 7;
        int yy[3];
        yy[0] = (y == 0) ? 1 : y - 1;
        yy[1] = y;
        yy[2] = (y == 255) ? 254 : y + 1;

        if (NORM_IN && b != cur_b) {
            nm = *(const float2*)(meanv + b * 64 + 2 * lane);
            nr = *(const float2*)(rstdv + b * 64 + 2 * lane);
            cur_b = b;
        }

        if (USE_K) {
            float* sg = (float*)(sb + (A_OFF + g * 32768));   // [3][132] staging
            const float* gp = guide + ((size_t)b << 16);
            for (int i = tg; i < 390; i += 256) {
                int ry = i / 130, j = i - ry * 130;
                sg[ry * 132 + j] = gp[yy[ry] * 256 + reflx(x0 - 1 + j)];
            }
            GBAR(barid);
            for (int i = tg; i < 1152; i += 256) {
                int t9 = i >> 7, px = i & 127;
                float d = sg[(t9 / 3) * 132 + px + (t9 % 3)] - sg[132 + px + 1];
                sk[i] = __expf(-0.5f * d * d);
            }
            GBAR(barid);
        }

        float acc[2][4][4];
#pragma unroll
        for (int mi = 0; mi < 2; ++mi)
#pragma unroll
            for (int ni = 0; ni < 4; ++ni)
#pragma unroll
                for (int q = 0; q < 4; ++q) acc[mi][ni][q] = 0.f;

        for (int t9 = 0; t9 < 9; ++t9) {
            // ---- build A (hi/lo) for this tap ----
            const int ysrc = yy[t9 / 3];
            const int dx   = (t9 % 3) - 1;
            const float* kk = sk + t9 * 128;
            const float* rowbase =
                in + ((((size_t)b * 256 + ysrc) * 256) << 6) + 2 * lane;
#pragma unroll 4
            for (int r = wg; r < 128; r += 8) {
                int xsrc = x0 + r + dx;
                xsrc = xsrc < 0 ? 1 : (xsrc > 255 ? 254 : xsrc);
                float2 v = *(const float2*)(rowbase + ((size_t)xsrc << 6));
                float p0 = v.x, p1 = v.y;
                if (NORM_IN) {
                    p0 = fmaxf((p0 - nm.x) * nr.x, 0.f);
                    p1 = fmaxf((p1 - nm.y) * nr.y, 0.f);
                }
                if (USE_K) { float s = kk[r]; p0 *= s; p1 *= s; }
                __nv_bfloat162 h2 = __float22bfloat162_rn(make_float2(p0, p1));
                float l0 = p0 - __bfloat162float(h2.x);
                float l1 = p1 - __bfloat162float(h2.y);
                __nv_bfloat162 lo2 = __float22bfloat162_rn(make_float2(l0, l1));
                u32 off = swz((u32)(r * 128 + lane * 4));
                *(u32*)(sb + (aHi - smem0) + off) = *(u32*)&h2;
                *(u32*)(sb + (aLo - smem0) + off) = *(u32*)&lo2;
            }
            GBAR(barid);

            // ---- 3 passes: Ahi*Whi, Alo*Whi, Ahi*Wlo ----
            const u32 wHi = smem0 + W_OFF + t9 * 16384;
            const u32 wLo = wHi + 8192;
            const u32 aRowOff = (u32)((wm * 32 + (lane & 15)) * 128 + (lane >> 4) * 16);
            const u32 bRowOff = (u32)((wn * 32 + ((lane >> 4) << 3) + (lane & 7)) * 128
                                      + ((lane >> 3) & 1) * 16);
#pragma unroll
            for (int pass = 0; pass < 3; ++pass) {
                const u32 Ab = (pass == 1) ? aLo : aHi;
                const u32 Wb = (pass == 2) ? wLo : wHi;
#pragma unroll
                for (int ks = 0; ks < 4; ++ks) {
                    u32 af[2][4], bfr[2][4];
#pragma unroll
                    for (int mi = 0; mi < 2; ++mi)
                        ldsm4(af[mi], Ab + swz(aRowOff + mi * 16 * 128 + ks * 32));
#pragma unroll
                    for (int p = 0; p < 2; ++p)
                        ldsm4(bfr[p], Wb + swz(bRowOff + p * 16 * 128 + ks * 32));
#pragma unroll
                    for (int mi = 0; mi < 2; ++mi)
#pragma unroll
                        for (int ni = 0; ni < 4; ++ni)
                            mma16816(acc[mi][ni], af[mi], &bfr[ni >> 1][(ni & 1) * 2]);
                }
            }
            GBAR(barid);   // all warps done reading A before next build
        }

        // ---- epilogue ----
        const int row = lane >> 2;
        if (!FINAL) {
            // direct NHWC float2 stores + fused instance-norm sums
            float sv[8], sq2[8];
#pragma unroll
            for (int q = 0; q < 8; ++q) { sv[q] = 0.f; sq2[q] = 0.f; }
            const size_t rowb = ((((size_t)b * 256 + y) * 256 + x0) << 6);
#pragma unroll
            for (int mi = 0; mi < 2; ++mi) {
                int px = wm * 32 + mi * 16 + row;
                float* p0 = out + rowb + ((size_t)px << 6);
                float* p1 = p0 + (8 << 6);
#pragma unroll
                for (int ni = 0; ni < 4; ++ni) {
                    int oc = wn * 32 + ni * 8 + cp;
                    float v0 = acc[mi][ni][0] + biasv[ni].x;
                    float v1 = acc[mi][ni][1] + biasv[ni].y;
                    float v2 = acc[mi][ni][2] + biasv[ni].x;
                    float v3 = acc[mi][ni][3] + biasv[ni].y;
                    *(float2*)(p0 + oc) = make_float2(v0, v1);
                    *(float2*)(p1 + oc) = make_float2(v2, v3);
                    sv[ni * 2 + 0] += v0 + v2;
                    sv[ni * 2 + 1] += v1 + v3;
                    sq2[ni * 2 + 0] = fmaf(v0, v0, fmaf(v2, v2, sq2[ni * 2 + 0]));
                    sq2[ni * 2 + 1] = fmaf(v1, v1, fmaf(v3, v3, sq2[ni * 2 + 1]));
                }
            }
#pragma unroll
            for (int off = 4; off < 32; off <<= 1)
#pragma unroll
                for (int q = 0; q < 8; ++q) {
                    sv[q]  += __shfl_xor_sync(0xffffffffu, sv[q],  off);
                    sq2[q] += __shfl_xor_sync(0xffffffffu, sq2[q], off);
                }
            if (lane < 4) {
#pragma unroll
                for (int ni = 0; ni < 4; ++ni) {
                    int oc = b * 64 + wn * 32 + ni * 8 + lane * 2;
                    atomicAdd(&sums[oc],     sv[ni * 2 + 0]);
                    atomicAdd(&sums[oc + 1], sv[ni * 2 + 1]);
                    atomicAdd(&sumsqs[oc],     sq2[ni * 2 + 0]);
                    atomicAdd(&sumsqs[oc + 1], sq2[ni * 2 + 1]);
                }
            }
        } else {
            // NCHW + bias + relu via two 64-px smem phases (group A region)
            float* epi = (float*)(sb + A_OFF + g * 32768);   // [64][66]
#pragma unroll
            for (int phase = 0; phase < 2; ++phase) {
                if ((wm >> 1) == phase) {
                    int pxl = (wm & 1) * 32 + row;
#pragma unroll
                    for (int mi = 0; mi < 2; ++mi)
#pragma unroll
                        for (int ni = 0; ni < 4; ++ni) {
                            int oc = wn * 32 + ni * 8 + cp;
                            int pl = pxl + mi * 16;
                            *(float2*)&epi[pl * 66 + oc] =
                                make_float2(acc[mi][ni][0], acc[mi][ni][1]);
                            *(float2*)&epi[(pl + 8) * 66 + oc] =
                                make_float2(acc[mi][ni][2], acc[mi][ni][3]);
                        }
                }
                GBAR(barid);
                for (int i = tg; i < 4096; i += 256) {
                    int oc = i >> 6, px = i & 63;
                    float bv = *(const float*)(sb + BIAS_OFF + oc * 4);
                    float v = fmaxf(epi[px * 66 + oc] + bv, 0.f);
                    out[((size_t)(b * 64 + oc) << 16) + y * 256 + x0 + phase * 64 + px] = v;
                }
                GBAR(barid);
            }
        }
    }
}

// =======================================================================
// Aux kernels (NHWC)
// =======================================================================
__global__ void conv1x1_kernel(const float* __restrict__ x,
                               const float* __restrict__ w0,
                               const float* __restrict__ b0,
                               float* __restrict__ h)   // NHWC out
{
    __shared__ float sw[64], sbv[64];
    int tid = threadIdx.x;
    if (tid < 64) { sw[tid] = w0[tid]; sbv[tid] = b0[tid]; }
    __syncthreads();
    int b = blockIdx.x >> 8, y = blockIdx.x & 255;
    const float* xr = x + ((size_t)b << 16) + y * 256;
    float* ob = h + ((((size_t)b * 256 + y) * 256) << 6);
    int c = tid & 63;
    float wv = sw[c], bv = sbv[c];
    for (int i = 0; i < 64; ++i) {
        int px = i * 4 + (tid >> 6);
        ob[((size_t)px << 6) + c] = fmaf(wv, xr[px], bv);
    }
}

__global__ void finalize_stats_kernel(float* __restrict__ sums,
                                      float* __restrict__ sumsqs,
                                      float* __restrict__ meanv,
                                      float* __restrict__ rstdv)
{
    int bc = threadIdx.x;
    float m   = sums[bc]   * (1.0f / 65536.0f);
    float var = sumsqs[bc] * (1.0f / 65536.0f) - m * m;
    meanv[bc] = m;
    rstdv[bc] = rsqrtf(var + 1e-5f);
    sums[bc] = 0.f;
    sumsqs[bc] = 0.f;
}

__global__ void combine_kernel(float4* __restrict__ h,         // NHWC
                               const float4* __restrict__ t2,
                               const float* __restrict__ meanv,
                               const float* __restrict__ rstdv)
{
    size_t i = (size_t)blockIdx.x * 256 + threadIdx.x;   // 4,194,304 float4
    int c4 = (int)(i & 15);
    int b  = (int)(i >> 20);
    float4 m4 = ((const float4*)meanv)[(b << 4) + c4];
    float4 r4 = ((const float4*)rstdv)[(b << 4) + c4];
    float4 t = t2[i];
    float4 hv = h[i];
    hv.x = fmaxf(hv.x + (t.x - m4.x) * r4.x, 0.f);
    hv.y = fmaxf(hv.y + (t.y - m4.y) * r4.y, 0.f);
    hv.z = fmaxf(hv.z + (t.z - m4.z) * r4.z, 0.f);
    hv.w = fmaxf(hv.w + (t.w - m4.w) * r4.w, 0.f);
    h[i] = hv;
}

// =======================================================================
// launcher
// =======================================================================
extern "C" void kernel_launch(void* const* d_in, const int* in_sizes, int n_in,
                              void* d_out, int out_size)
{
    (void)in_sizes; (void)n_in; (void)out_size;
    const float* x  = (const float*)d_in[0];
    const float* w0 = (const float*)d_in[2];
    const float* b0 = (const float*)d_in[3];
    const float* wf = (const float*)d_in[4];
    const float* bf = (const float*)d_in[5];
    const float* wa[3] = {(const float*)d_in[6],  (const float*)d_in[10], (const float*)d_in[14]};
    const float* ba[3] = {(const float*)d_in[7],  (const float*)d_in[11], (const float*)d_in[15]};
    const float* wb[3] = {(const float*)d_in[8],  (const float*)d_in[12], (const float*)d_in[16]};
    const float* bb[3] = {(const float*)d_in[9],  (const float*)d_in[13], (const float*)d_in[17]};

    float *h, *t1, *t2, *mv, *rv, *sm, *sq;
    cudaGetSymbolAddress((void**)&h,  g_h);
    cudaGetSymbolAddress((void**)&t1, g_t1);
    cudaGetSymbolAddress((void**)&t2, g_t2);
    cudaGetSymbolAddress((void**)&mv, g_mean);
    cudaGetSymbolAddress((void**)&rv, g_rstd);
    cudaGetSymbolAddress((void**)&sm, g_sum);
    cudaGetSymbolAddress((void**)&sq, g_sumsq);

    cudaFuncSetAttribute(pac_mma_kernel<false, true,  false>,
                         cudaFuncAttributeMaxDynamicSharedMemorySize, DSMEM);
    cudaFuncSetAttribute(pac_mma_kernel<true,  true,  false>,
                         cudaFuncAttributeMaxDynamicSharedMemorySize, DSMEM);
    cudaFuncSetAttribute(pac_mma_kernel<false, false, true>,
                         cudaFuncAttributeMaxDynamicSharedMemorySize, DSMEM);

    conv1x1_kernel<<<1024, 256>>>(x, w0, b0, h);

    for (int r = 0; r < 3; ++r) {
        pac_mma_kernel<false, true, false><<<148, 512, DSMEM>>>(
            h, x, wa[r], ba[r], nullptr, nullptr, t1, sm, sq);
        finalize_stats_kernel<<<1, 256>>>(sm, sq, mv, rv);

        pac_mma_kernel<true, true, false><<<148, 512, DSMEM>>>(
            t1, x, wb[r], bb[r], mv, rv, t2, sm, sq);
        finalize_stats_kernel<<<1, 256>>>(sm, sq, mv, rv);

        combine_kernel<<<16384, 256>>>((float4*)h, (const float4*)t2, mv, rv);
    }

    pac_mma_kernel<false, false, true><<<148, 512, DSMEM>>>(
        h, x, wf, bf, nullptr, nullptr, (float*)d_out, sm, sq);
}

// round 8
// speedup vs baseline: 4.1126x; 1.2706x over previous
#include <cuda_runtime.h>
#include <cuda_bf16.h>
#include <cstdint>
#include <cstddef>

typedef unsigned long long u64;
typedef unsigned int u32;

// ---------------- device scratch (no cudaMalloc allowed) ----------------
// NHWC feature buffers [b][y][x][c], 4*256*256*64 floats each
__device__ float g_h [16777216];
__device__ float g_t1[16777216];
__device__ float g_t2[16777216];
__device__ __align__(16) float g_mean[256];
__device__ __align__(16) float g_rstd[256];
__device__ __align__(16) float g_sum[256];     // zero-init; finalize re-zeroes
__device__ __align__(16) float g_sumsq[256];

// ---------------- helpers ----------------
__device__ __forceinline__ u32 smem_u32(const void* p) {
    u32 a;
    asm("{ .reg .u64 t; cvta.to.shared.u64 t, %1; cvt.u32.u64 %0, t; }"
        : "=r"(a) : "l"(p));
    return a;
}
__device__ __forceinline__ u32 swz(u32 off) { return off ^ ((off >> 3) & 0x70); }
__device__ __forceinline__ int reflx(int i) { return i < 0 ? 1 : (i >= 256 ? 254 : i); }

__device__ __forceinline__ void ldsm4(u32* r, u32 addr) {
    asm volatile("ldmatrix.sync.aligned.m8n8.x4.shared.b16 {%0,%1,%2,%3}, [%4];"
        : "=r"(r[0]), "=r"(r[1]), "=r"(r[2]), "=r"(r[3]) : "r"(addr));
}
__device__ __forceinline__ void mma16816(float* d, const u32* a, const u32* b) {
    asm volatile(
        "mma.sync.aligned.m16n8k16.row.col.f32.bf16.bf16.f32 "
        "{%0,%1,%2,%3}, {%4,%5,%6,%7}, {%8,%9}, {%0,%1,%2,%3};"
        : "+f"(d[0]), "+f"(d[1]), "+f"(d[2]), "+f"(d[3])
        : "r"(a[0]), "r"(a[1]), "r"(a[2]), "r"(a[3]), "r"(b[0]), "r"(b[1]));
}
#define GBAR(id) asm volatile("bar.sync %0, 256;" :: "r"(id) : "memory")

// ---------------- smem layout (relative to 1024-aligned base) ----------------
// [0     : 256   ) bias (64 f32)
// [512   : 9728  ) s_k  float [2 groups][9][128]
// [10240 : 157696) W tiles: [tap][hi/lo][64 oc][128B row], swizzled (9*16384)
// [157696: 225280) A tiles per group (33792 B): raw x rows for one ky,
//                  130 rows x 128B, hi then lo (guide staging / FINAL epi overlay)
#define BIAS_OFF  0
#define K_OFF     512
#define W_OFF     10240
#define A_OFF     157696
#define A_STRIDE  33792
#define A_LO_REL  16896
#define DSMEM     (157696 + 2 * 33792 + 1024)

// =======================================================================
// PAC conv via mma.sync, shifted-ldmatrix implicit GEMM.
// bf16 hi/lo split (3 passes), fp32 accum; guide kernel k applied in fp32
// on per-tap register accumulators. Persistent, 512 thr, 2 tile groups.
// in NHWC; out NHWC + fused stats (FINAL: NCHW + relu, no stats).
// =======================================================================
template <bool NORM_IN, bool USE_K, bool FINAL>
__global__ void __launch_bounds__(512, 1)
pac_mma_kernel(const float* __restrict__ in,
               const float* __restrict__ guide,
               const float* __restrict__ w,      // [64][64][3][3] fp32
               const float* __restrict__ bias,
               const float* __restrict__ meanv,
               const float* __restrict__ rstdv,
               float* __restrict__ out,
               float* __restrict__ sums,
               float* __restrict__ sumsqs)
{
    extern __shared__ __align__(16) unsigned char dyn[];
    u32 raw0  = smem_u32(dyn);
    u32 smem0 = (raw0 + 1023) & ~1023u;
    unsigned char* sb = dyn + (smem0 - raw0);

    const int tid  = threadIdx.x;
    const int warp = tid >> 5;
    const int lane = tid & 31;
    const int g    = warp >> 3;        // tile group 0/1
    const int wg   = warp & 7;         // warp within group
    const int tg   = wg * 32 + lane;   // thread within group (0..255)
    const int wm   = wg >> 1;          // 0..3 : 32-px group
    const int wn   = wg & 1;           // 0..1 : 32-oc group
    const int barid = 1 + g;

    // ---- one-time: weights (hi/lo, swizzled rows) + bias ----
    for (int i = tid; i < 36864; i += 512) {
        int oc  = i / 576;
        int r   = i - oc * 576;
        int c   = r / 9;
        int tap = r - c * 9;
        float wv = w[i];
        __nv_bfloat16 hb = __float2bfloat16(wv);
        __nv_bfloat16 lb = __float2bfloat16(wv - __bfloat162float(hb));
        u32 off = swz((u32)(oc * 128 + c * 2));
        *(__nv_bfloat16*)(sb + W_OFF + tap * 16384 +        off) = hb;
        *(__nv_bfloat16*)(sb + W_OFF + tap * 16384 + 8192 + off) = lb;
    }
    if (tid < 64) *(float*)(sb + BIAS_OFF + tid * 4) = bias[tid];
    __syncthreads();

    float2 nm = make_float2(0.f, 0.f), nr = make_float2(1.f, 1.f);
    int cur_b = -1;

    const u32 aHi = smem0 + A_OFF + g * A_STRIDE;
    const u32 aLo = aHi + A_LO_REL;
    float* sk = (float*)(sb + K_OFF + g * 4608);
    const int cp  = (lane & 3) * 2;
    const int row4 = lane >> 2;

    // B-operand ldsm row offset (32 oc per warp via two x4 loads)
    const u32 bRowOff = (u32)((wn * 32 + ((lane >> 4) << 3) + (lane & 7)) * 128
                              + ((lane >> 3) & 1) * 16);

    for (int tile = blockIdx.x * 2 + g; tile < 2048; tile += gridDim.x * 2) {
        const int b   = tile >> 9;
        const int rem = tile & 511;
        const int y   = rem >> 1;
        const int x0  = (rem & 1) << 7;
        int yy[3];
        yy[0] = (y == 0) ? 1 : y - 1;
        yy[1] = y;
        yy[2] = (y == 255) ? 254 : y + 1;

        if (NORM_IN && b != cur_b) {
            nm = *(const float2*)(meanv + b * 64 + 2 * lane);
            nr = *(const float2*)(rstdv + b * 64 + 2 * lane);
            cur_b = b;
        }

        if (USE_K) {
            float* sg = (float*)(sb + A_OFF + g * A_STRIDE);   // [3][132] staging
            const float* gp = guide + ((size_t)b << 16);
            for (int i = tg; i < 390; i += 256) {
                int ry = i / 130, j = i - ry * 130;
                sg[ry * 132 + j] = gp[yy[ry] * 256 + reflx(x0 - 1 + j)];
            }
            GBAR(barid);
            for (int i = tg; i < 1152; i += 256) {
                int t9 = i >> 7, px = i & 127;
                float d = sg[(t9 / 3) * 132 + px + (t9 % 3)] - sg[132 + px + 1];
                sk[i] = __expf(-0.5f * d * d);
            }
            GBAR(barid);
        }

        float acc[2][4][4];
#pragma unroll
        for (int mi = 0; mi < 2; ++mi)
#pragma unroll
            for (int ni = 0; ni < 4; ++ni)
#pragma unroll
                for (int q = 0; q < 4; ++q) acc[mi][ni][q] = 0.f;

        for (int ky = 0; ky < 3; ++ky) {
            // ---- build raw (normed) x tile for this ky: 130 rows hi/lo ----
            const float* rowbase =
                in + ((((size_t)b * 256 + yy[ky]) * 256) << 6) + 2 * lane;
            for (int r = wg; r < 130; r += 8) {
                int xg = x0 - 1 + r;
                xg = xg < 0 ? 1 : (xg > 255 ? 254 : xg);
                float2 v = *(const float2*)(rowbase + ((size_t)xg << 6));
                float p0 = v.x, p1 = v.y;
                if (NORM_IN) {
                    p0 = fmaxf((p0 - nm.x) * nr.x, 0.f);
                    p1 = fmaxf((p1 - nm.y) * nr.y, 0.f);
                }
                __nv_bfloat162 h2 = __float22bfloat162_rn(make_float2(p0, p1));
                float l0 = p0 - __bfloat162float(h2.x);
                float l1 = p1 - __bfloat162float(h2.y);
                __nv_bfloat162 lo2 = __float22bfloat162_rn(make_float2(l0, l1));
                u32 off = swz((u32)(r * 128 + lane * 4));
                *(u32*)(sb + (A_OFF + g * A_STRIDE) + off)            = *(u32*)&h2;
                *(u32*)(sb + (A_OFF + g * A_STRIDE) + A_LO_REL + off) = *(u32*)&lo2;
            }
            GBAR(barid);

#pragma unroll
            for (int kx = 0; kx < 3; ++kx) {
                const int t9 = ky * 3 + kx;
                const u32 wHi = smem0 + W_OFF + t9 * 16384;
                const u32 wLo = wHi + 8192;
                // shifted A row offsets (row = px + kx in 130-row tile)
                u32 arow[2];
#pragma unroll
                for (int mi = 0; mi < 2; ++mi)
                    arow[mi] = (u32)((wm * 32 + (lane & 15) + mi * 16 + kx) * 128
                                     + (lane >> 4) * 16);

                float atap[2][4][4];
                if (USE_K) {
#pragma unroll
                    for (int mi = 0; mi < 2; ++mi)
#pragma unroll
                        for (int ni = 0; ni < 4; ++ni)
#pragma unroll
                            for (int q = 0; q < 4; ++q) atap[mi][ni][q] = 0.f;
                }
#define DST(mi, ni) (USE_K ? atap[mi][ni] : acc[mi][ni])

                // phase 1: A-hi x (W-hi, W-lo)
#pragma unroll
                for (int ks = 0; ks < 4; ++ks) {
                    u32 af[2][4], bh[2][4], bl[2][4];
#pragma unroll
                    for (int mi = 0; mi < 2; ++mi)
                        ldsm4(af[mi], aHi + swz(arow[mi] + ks * 32));
#pragma unroll
                    for (int p = 0; p < 2; ++p) {
                        ldsm4(bh[p], wHi + swz(bRowOff + p * 16 * 128 + ks * 32));
                        ldsm4(bl[p], wLo + swz(bRowOff + p * 16 * 128 + ks * 32));
                    }
#pragma unroll
                    for (int mi = 0; mi < 2; ++mi)
#pragma unroll
                        for (int ni = 0; ni < 4; ++ni) {
                            mma16816(DST(mi, ni), af[mi], &bh[ni >> 1][(ni & 1) * 2]);
                            mma16816(DST(mi, ni), af[mi], &bl[ni >> 1][(ni & 1) * 2]);
                        }
                }
                // phase 2: A-lo x W-hi
#pragma unroll
                for (int ks = 0; ks < 4; ++ks) {
                    u32 af[2][4], bh[2][4];
#pragma unroll
                    for (int mi = 0; mi < 2; ++mi)
                        ldsm4(af[mi], aLo + swz(arow[mi] + ks * 32));
#pragma unroll
                    for (int p = 0; p < 2; ++p)
                        ldsm4(bh[p], wHi + swz(bRowOff + p * 16 * 128 + ks * 32));
#pragma unroll
                    for (int mi = 0; mi < 2; ++mi)
#pragma unroll
                        for (int ni = 0; ni < 4; ++ni)
                            mma16816(DST(mi, ni), af[mi], &bh[ni >> 1][(ni & 1) * 2]);
                }
#undef DST

                if (USE_K) {
                    float kv[2][2];
#pragma unroll
                    for (int mi = 0; mi < 2; ++mi) {
                        kv[mi][0] = sk[t9 * 128 + wm * 32 + mi * 16 + row4];
                        kv[mi][1] = sk[t9 * 128 + wm * 32 + mi * 16 + row4 + 8];
                    }
#pragma unroll
                    for (int mi = 0; mi < 2; ++mi)
#pragma unroll
                        for (int ni = 0; ni < 4; ++ni) {
                            acc[mi][ni][0] = fmaf(kv[mi][0], atap[mi][ni][0], acc[mi][ni][0]);
                            acc[mi][ni][1] = fmaf(kv[mi][0], atap[mi][ni][1], acc[mi][ni][1]);
                            acc[mi][ni][2] = fmaf(kv[mi][1], atap[mi][ni][2], acc[mi][ni][2]);
                            acc[mi][ni][3] = fmaf(kv[mi][1], atap[mi][ni][3], acc[mi][ni][3]);
                        }
                }
            }
            GBAR(barid);   // all warps done reading A before next ky build
        }

        // ---- epilogue ----
        if (!FINAL) {
            // direct NHWC float2 stores + fused instance-norm sums
            float2 biasv[4];
#pragma unroll
            for (int ni = 0; ni < 4; ++ni)
                biasv[ni] = *(const float2*)(sb + BIAS_OFF + (wn * 32 + ni * 8 + cp) * 4);
            float sv[8], sq2[8];
#pragma unroll
            for (int q = 0; q < 8; ++q) { sv[q] = 0.f; sq2[q] = 0.f; }
            const size_t rowb = ((((size_t)b * 256 + y) * 256 + x0) << 6);
#pragma unroll
            for (int mi = 0; mi < 2; ++mi) {
                int px = wm * 32 + mi * 16 + row4;
                float* p0 = out + rowb + ((size_t)px << 6);
                float* p1 = p0 + (8 << 6);
#pragma unroll
                for (int ni = 0; ni < 4; ++ni) {
                    int oc = wn * 32 + ni * 8 + cp;
                    float v0 = acc[mi][ni][0] + biasv[ni].x;
                    float v1 = acc[mi][ni][1] + biasv[ni].y;
                    float v2 = acc[mi][ni][2] + biasv[ni].x;
                    float v3 = acc[mi][ni][3] + biasv[ni].y;
                    *(float2*)(p0 + oc) = make_float2(v0, v1);
                    *(float2*)(p1 + oc) = make_float2(v2, v3);
                    sv[ni * 2 + 0] += v0 + v2;
                    sv[ni * 2 + 1] += v1 + v3;
                    sq2[ni * 2 + 0] = fmaf(v0, v0, fmaf(v2, v2, sq2[ni * 2 + 0]));
                    sq2[ni * 2 + 1] = fmaf(v1, v1, fmaf(v3, v3, sq2[ni * 2 + 1]));
                }
            }
#pragma unroll
            for (int off = 4; off < 32; off <<= 1)
#pragma unroll
                for (int q = 0; q < 8; ++q) {
                    sv[q]  += __shfl_xor_sync(0xffffffffu, sv[q],  off);
                    sq2[q] += __shfl_xor_sync(0xffffffffu, sq2[q], off);
                }
            if (lane < 4) {
#pragma unroll
                for (int ni = 0; ni < 4; ++ni) {
                    int oc = b * 64 + wn * 32 + ni * 8 + lane * 2;
                    atomicAdd(&sums[oc],     sv[ni * 2 + 0]);
                    atomicAdd(&sums[oc + 1], sv[ni * 2 + 1]);
                    atomicAdd(&sumsqs[oc],     sq2[ni * 2 + 0]);
                    atomicAdd(&sumsqs[oc + 1], sq2[ni * 2 + 1]);
                }
            }
        } else {
            // NCHW + bias + relu via two 64-px smem phases (A region overlay)
            float* epi = (float*)(sb + A_OFF + g * A_STRIDE);   // [64][66]
#pragma unroll
            for (int phase = 0; phase < 2; ++phase) {
                if ((wm >> 1) == phase) {
                    int pxl = (wm & 1) * 32 + row4;
#pragma unroll
                    for (int mi = 0; mi < 2; ++mi)
#pragma unroll
                        for (int ni = 0; ni < 4; ++ni) {
                            int oc = wn * 32 + ni * 8 + cp;
                            int pl = pxl + mi * 16;
                            *(float2*)&epi[pl * 66 + oc] =
                                make_float2(acc[mi][ni][0], acc[mi][ni][1]);
                            *(float2*)&epi[(pl + 8) * 66 + oc] =
                                make_float2(acc[mi][ni][2], acc[mi][ni][3]);
                        }
                }
                GBAR(barid);
                for (int i = tg; i < 4096; i += 256) {
                    int oc = i >> 6, px = i & 63;
                    float bv = *(const float*)(sb + BIAS_OFF + oc * 4);
                    float v = fmaxf(epi[px * 66 + oc] + bv, 0.f);
                    out[((size_t)(b * 64 + oc) << 16) + y * 256 + x0 + phase * 64 + px] = v;
                }
                GBAR(barid);
            }
        }
    }
}

// =======================================================================
// Aux kernels (NHWC)
// =======================================================================
__global__ void conv1x1_kernel(const float* __restrict__ x,
                               const float* __restrict__ w0,
                               const float* __restrict__ b0,
                               float* __restrict__ h)   // NHWC out
{
    __shared__ float sw[64], sbv[64];
    int tid = threadIdx.x;
    if (tid < 64) { sw[tid] = w0[tid]; sbv[tid] = b0[tid]; }
    __syncthreads();
    int b = blockIdx.x >> 8, y = blockIdx.x & 255;
    const float* xr = x + ((size_t)b << 16) + y * 256;
    float* ob = h + ((((size_t)b * 256 + y) * 256) << 6);
    int c = tid & 63;
    float wv = sw[c], bv = sbv[c];
    for (int i = 0; i < 64; ++i) {
        int px = i * 4 + (tid >> 6);
        ob[((size_t)px << 6) + c] = fmaf(wv, xr[px], bv);
    }
}

__global__ void finalize_stats_kernel(float* __restrict__ sums,
                                      float* __restrict__ sumsqs,
                                      float* __restrict__ meanv,
                                      float* __restrict__ rstdv)
{
    int bc = threadIdx.x;
    float m   = sums[bc]   * (1.0f / 65536.0f);
    float var = sumsqs[bc] * (1.0f / 65536.0f) - m * m;
    meanv[bc] = m;
    rstdv[bc] = rsqrtf(var + 1e-5f);
    sums[bc] = 0.f;
    sumsqs[bc] = 0.f;
}

__global__ void combine_kernel(float4* __restrict__ h,         // NHWC
                               const float4* __restrict__ t2,
                               const float* __restrict__ meanv,
                               const float* __restrict__ rstdv)
{
    size_t i = (size_t)blockIdx.x * 256 + threadIdx.x;   // 4,194,304 float4
    int c4 = (int)(i & 15);
    int b  = (int)(i >> 20);
    float4 m4 = ((const float4*)meanv)[(b << 4) + c4];
    float4 r4 = ((const float4*)rstdv)[(b << 4) + c4];
    float4 t = t2[i];
    float4 hv = h[i];
    hv.x = fmaxf(hv.x + (t.x - m4.x) * r4.x, 0.f);
    hv.y = fmaxf(hv.y + (t.y - m4.y) * r4.y, 0.f);
    hv.z = fmaxf(hv.z + (t.z - m4.z) * r4.z, 0.f);
    hv.w = fmaxf(hv.w + (t.w - m4.w) * r4.w, 0.f);
    h[i] = hv;
}

// =======================================================================
// launcher
// =======================================================================
extern "C" void kernel_launch(void* const* d_in, const int* in_sizes, int n_in,
                              void* d_out, int out_size)
{
    (void)in_sizes; (void)n_in; (void)out_size;
    const float* x  = (const float*)d_in[0];
    const float* w0 = (const float*)d_in[2];
    const float* b0 = (const float*)d_in[3];
    const float* wf = (const float*)d_in[4];
    const float* bf = (const float*)d_in[5];
    const float* wa[3] = {(const float*)d_in[6],  (const float*)d_in[10], (const float*)d_in[14]};
    const float* ba[3] = {(const float*)d_in[7],  (const float*)d_in[11], (const float*)d_in[15]};
    const float* wb[3] = {(const float*)d_in[8],  (const float*)d_in[12], (const float*)d_in[16]};
    const float* bb[3] = {(const float*)d_in[9],  (const float*)d_in[13], (const float*)d_in[17]};

    float *h, *t1, *t2, *mv, *rv, *sm, *sq;
    cudaGetSymbolAddress((void**)&h,  g_h);
    cudaGetSymbolAddress((void**)&t1, g_t1);
    cudaGetSymbolAddress((void**)&t2, g_t2);
    cudaGetSymbolAddress((void**)&mv, g_mean);
    cudaGetSymbolAddress((void**)&rv, g_rstd);
    cudaGetSymbolAddress((void**)&sm, g_sum);
    cudaGetSymbolAddress((void**)&sq, g_sumsq);

    cudaFuncSetAttribute(pac_mma_kernel<false, true,  false>,
                         cudaFuncAttributeMaxDynamicSharedMemorySize, DSMEM);
    cudaFuncSetAttribute(pac_mma_kernel<true,  true,  false>,
                         cudaFuncAttributeMaxDynamicSharedMemorySize, DSMEM);
    cudaFuncSetAttribute(pac_mma_kernel<false, false, true>,
                         cudaFuncAttributeMaxDynamicSharedMemorySize, DSMEM);

    conv1x1_kernel<<<1024, 256>>>(x, w0, b0, h);

    for (int r = 0; r < 3; ++r) {
        pac_mma_kernel<false, true, false><<<148, 512, DSMEM>>>(
            h, x, wa[r], ba[r], nullptr, nullptr, t1, sm, sq);
        finalize_stats_kernel<<<1, 256>>>(sm, sq, mv, rv);

        pac_mma_kernel<true, true, false><<<148, 512, DSMEM>>>(
            t1, x, wb[r], bb[r], mv, rv, t2, sm, sq);
        finalize_stats_kernel<<<1, 256>>>(sm, sq, mv, rv);

        combine_kernel<<<16384, 256>>>((float4*)h, (const float4*)t2, mv, rv);
    }

    pac_mma_kernel<false, false, true><<<148, 512, DSMEM>>>(
        h, x, wf, bf, nullptr, nullptr, (float*)d_out, sm, sq);
}

// round 9
// speedup vs baseline: 4.4494x; 1.0819x over previous
#include <cuda_runtime.h>
#include <cuda_bf16.h>
#include <cstdint>
#include <cstddef>

typedef unsigned long long u64;
typedef unsigned int u32;

// ---------------- device scratch (no cudaMalloc allowed) ----------------
// NHWC feature buffers [b][y][x][c], 4*256*256*64 floats each
__device__ float g_h [16777216];
__device__ float g_t1[16777216];
__device__ float g_t2[16777216];
__device__ __align__(16) float g_mean[256];
__device__ __align__(16) float g_rstd[256];
__device__ __align__(16) float g_sum[256];     // zero-init; finalize re-zeroes
__device__ __align__(16) float g_sumsq[256];

// ---------------- helpers ----------------
__device__ __forceinline__ u32 smem_u32(const void* p) {
    u32 a;
    asm("{ .reg .u64 t; cvta.to.shared.u64 t, %1; cvt.u32.u64 %0, t; }"
        : "=r"(a) : "l"(p));
    return a;
}
__device__ __forceinline__ u32 swz(u32 off) { return off ^ ((off >> 3) & 0x70); }
__device__ __forceinline__ int reflx(int i) { return i < 0 ? 1 : (i >= 256 ? 254 : i); }

__device__ __forceinline__ void ldsm4(u32* r, u32 addr) {
    asm volatile("ldmatrix.sync.aligned.m8n8.x4.shared.b16 {%0,%1,%2,%3}, [%4];"
        : "=r"(r[0]), "=r"(r[1]), "=r"(r[2]), "=r"(r[3]) : "r"(addr));
}
__device__ __forceinline__ void mma16816(float* d, const u32* a, const u32* b) {
    asm volatile(
        "mma.sync.aligned.m16n8k16.row.col.f32.bf16.bf16.f32 "
        "{%0,%1,%2,%3}, {%4,%5,%6,%7}, {%8,%9}, {%0,%1,%2,%3};"
        : "+f"(d[0]), "+f"(d[1]), "+f"(d[2]), "+f"(d[3])
        : "r"(a[0]), "r"(a[1]), "r"(a[2]), "r"(a[3]), "r"(b[0]), "r"(b[1]));
}
#define GBAR(id) asm volatile("bar.sync %0, 256;" :: "r"(id) : "memory")

// ---------------- smem layout (relative to 1024-aligned base) ----------------
// [0     : 256   ) bias (64 f32)
// [512   : 9728  ) s_k  float [2 groups][9][128]
// [10240 : 157696) W tiles: [tap][hi/lo][64 oc][128B row], swizzled (9*16384)
// [157696: 225280) A tiles per group (33792 B): raw x rows for one ky,
//                  130 rows x 128B, hi then lo  (FINAL epi overlay)
#define BIAS_OFF  0
#define K_OFF     512
#define W_OFF     10240
#define A_OFF     157696
#define A_STRIDE  33792
#define A_LO_REL  16896
#define DSMEM     (157696 + 2 * 33792 + 1024)

// =======================================================================
// PAC conv via mma.sync, shifted-ldmatrix implicit GEMM.
// bf16 hi/lo split (3 passes, shared W-hi ldsm), fp32 accum; guide kernel
// applied in fp32 on per-tap register accumulators. 512 thr, 2 tile groups.
// in NHWC; out NHWC + fused stats (FINAL: NCHW + relu, no stats).
// =======================================================================
template <bool NORM_IN, bool USE_K, bool FINAL>
__global__ void __launch_bounds__(512, 1)
pac_mma_kernel(const float* __restrict__ in,
               const float* __restrict__ guide,
               const float* __restrict__ w,      // [64][64][3][3] fp32
               const float* __restrict__ bias,
               const float* __restrict__ meanv,
               const float* __restrict__ rstdv,
               float* __restrict__ out,
               float* __restrict__ sums,
               float* __restrict__ sumsqs)
{
    extern __shared__ __align__(16) unsigned char dyn[];
    u32 raw0  = smem_u32(dyn);
    u32 smem0 = (raw0 + 1023) & ~1023u;
    unsigned char* sb = dyn + (smem0 - raw0);

    const int tid  = threadIdx.x;
    const int warp = tid >> 5;
    const int lane = tid & 31;
    const int g    = warp >> 3;        // tile group 0/1
    const int wg   = warp & 7;         // warp within group
    const int tg   = wg * 32 + lane;   // thread within group (0..255)
    const int wm   = wg >> 1;          // 0..3 : 32-px group
    const int wn   = wg & 1;           // 0..1 : 32-oc group
    const int barid = 1 + g;

    // ---- one-time: weights (hi/lo, swizzled rows) + bias ----
    for (int i = tid; i < 36864; i += 512) {
        int oc  = i / 576;
        int r   = i - oc * 576;
        int c   = r / 9;
        int tap = r - c * 9;
        float wv = w[i];
        __nv_bfloat16 hb = __float2bfloat16(wv);
        __nv_bfloat16 lb = __float2bfloat16(wv - __bfloat162float(hb));
        u32 off = swz((u32)(oc * 128 + c * 2));
        *(__nv_bfloat16*)(sb + W_OFF + tap * 16384 +        off) = hb;
        *(__nv_bfloat16*)(sb + W_OFF + tap * 16384 + 8192 + off) = lb;
    }
    if (tid < 64) *(float*)(sb + BIAS_OFF + tid * 4) = bias[tid];
    __syncthreads();

    float2 nm = make_float2(0.f, 0.f), nr = make_float2(1.f, 1.f);
    int cur_b = -1;

    const u32 aHi = smem0 + A_OFF + g * A_STRIDE;
    const u32 aLo = aHi + A_LO_REL;
    float* sk = (float*)(sb + K_OFF + g * 4608);
    const int cp  = (lane & 3) * 2;
    const int row4 = lane >> 2;

    // B-operand ldsm row offset (32 oc per warp via two x4 loads)
    const u32 bRowOff = (u32)((wn * 32 + ((lane >> 4) << 3) + (lane & 7)) * 128
                              + ((lane >> 3) & 1) * 16);

    for (int tile = blockIdx.x * 2 + g; tile < 2048; tile += gridDim.x * 2) {
        const int b   = tile >> 9;
        const int rem = tile & 511;
        const int y   = rem >> 1;
        const int x0  = (rem & 1) << 7;
        int yy[3];
        yy[0] = (y == 0) ? 1 : y - 1;
        yy[1] = y;
        yy[2] = (y == 255) ? 254 : y + 1;

        if (NORM_IN && b != cur_b) {
            nm = *(const float2*)(meanv + b * 64 + 2 * lane);
            nr = *(const float2*)(rstdv + b * 64 + 2 * lane);
            cur_b = b;
        }

        if (USE_K) {
            // direct-LDG k build (guide rows are L1-hot; 9 LDG/thread).
            // Writes to sk become visible at the first build GBAR below;
            // prior-tile sk reads all precede the prior loop-end GBAR.
            const float* gp = guide + ((size_t)b << 16);
            const float* gc0 = gp + y * 256 + x0;
#pragma unroll
            for (int it = 0; it < 5; ++it) {
                int i = tg + it * 256;
                if (i < 1152) {
                    int t9 = i >> 7, px = i & 127;
                    float gs = gp[yy[t9 / 3] * 256 + reflx(x0 + px + (t9 % 3) - 1)];
                    float d  = gs - gc0[px];
                    sk[i] = __expf(-0.5f * d * d);
                }
            }
        }

        float acc[2][4][4];
#pragma unroll
        for (int mi = 0; mi < 2; ++mi)
#pragma unroll
            for (int ni = 0; ni < 4; ++ni)
#pragma unroll
                for (int q = 0; q < 4; ++q) acc[mi][ni][q] = 0.f;

        for (int ky = 0; ky < 3; ++ky) {
            // ---- build raw (normed) x tile for this ky: 130 rows hi/lo ----
            const float* rowbase =
                in + ((((size_t)b * 256 + yy[ky]) * 256) << 6) + 2 * lane;
            for (int r = wg; r < 130; r += 8) {
                int xg = x0 - 1 + r;
                xg = xg < 0 ? 1 : (xg > 255 ? 254 : xg);
                float2 v = *(const float2*)(rowbase + ((size_t)xg << 6));
                float p0 = v.x, p1 = v.y;
                if (NORM_IN) {
                    p0 = fmaxf((p0 - nm.x) * nr.x, 0.f);
                    p1 = fmaxf((p1 - nm.y) * nr.y, 0.f);
                }
                __nv_bfloat162 h2 = __float22bfloat162_rn(make_float2(p0, p1));
                float l0 = p0 - __bfloat162float(h2.x);
                float l1 = p1 - __bfloat162float(h2.y);
                __nv_bfloat162 lo2 = __float22bfloat162_rn(make_float2(l0, l1));
                u32 off = swz((u32)(r * 128 + lane * 4));
                *(u32*)(sb + (A_OFF + g * A_STRIDE) + off)            = *(u32*)&h2;
                *(u32*)(sb + (A_OFF + g * A_STRIDE) + A_LO_REL + off) = *(u32*)&lo2;
            }
            GBAR(barid);

#pragma unroll
            for (int kx = 0; kx < 3; ++kx) {
                const int t9 = ky * 3 + kx;
                const u32 wHi = smem0 + W_OFF + t9 * 16384;
                const u32 wLo = wHi + 8192;
                // shifted A row offsets (row = px + kx in 130-row tile)
                u32 arow[2];
#pragma unroll
                for (int mi = 0; mi < 2; ++mi)
                    arow[mi] = (u32)((wm * 32 + (lane & 15) + mi * 16 + kx) * 128
                                     + (lane >> 4) * 16);

                float atap[2][4][4];
                if (USE_K) {
#pragma unroll
                    for (int mi = 0; mi < 2; ++mi)
#pragma unroll
                        for (int ni = 0; ni < 4; ++ni)
#pragma unroll
                            for (int q = 0; q < 4; ++q) atap[mi][ni][q] = 0.f;
                }
#define DST(mi, ni) (USE_K ? atap[mi][ni] : acc[mi][ni])

                // merged 3-pass: per ks load afh/afl/bh, mma x2, swap bh->bl, mma
#pragma unroll
                for (int ks = 0; ks < 4; ++ks) {
                    u32 afh[2][4], afl[2][4], bb[2][4];
#pragma unroll
                    for (int mi = 0; mi < 2; ++mi) {
                        ldsm4(afh[mi], aHi + swz(arow[mi] + ks * 32));
                        ldsm4(afl[mi], aLo + swz(arow[mi] + ks * 32));
                    }
#pragma unroll
                    for (int p = 0; p < 2; ++p)
                        ldsm4(bb[p], wHi + swz(bRowOff + p * 16 * 128 + ks * 32));
#pragma unroll
                    for (int mi = 0; mi < 2; ++mi)
#pragma unroll
                        for (int ni = 0; ni < 4; ++ni) {
                            mma16816(DST(mi, ni), afh[mi], &bb[ni >> 1][(ni & 1) * 2]);
                            mma16816(DST(mi, ni), afl[mi], &bb[ni >> 1][(ni & 1) * 2]);
                        }
#pragma unroll
                    for (int p = 0; p < 2; ++p)
                        ldsm4(bb[p], wLo + swz(bRowOff + p * 16 * 128 + ks * 32));
#pragma unroll
                    for (int mi = 0; mi < 2; ++mi)
#pragma unroll
                        for (int ni = 0; ni < 4; ++ni)
                            mma16816(DST(mi, ni), afh[mi], &bb[ni >> 1][(ni & 1) * 2]);
                }
#undef DST

                if (USE_K) {
                    float kv[2][2];
#pragma unroll
                    for (int mi = 0; mi < 2; ++mi) {
                        kv[mi][0] = sk[t9 * 128 + wm * 32 + mi * 16 + row4];
                        kv[mi][1] = sk[t9 * 128 + wm * 32 + mi * 16 + row4 + 8];
                    }
#pragma unroll
                    for (int mi = 0; mi < 2; ++mi)
#pragma unroll
                        for (int ni = 0; ni < 4; ++ni) {
                            acc[mi][ni][0] = fmaf(kv[mi][0], atap[mi][ni][0], acc[mi][ni][0]);
                            acc[mi][ni][1] = fmaf(kv[mi][0], atap[mi][ni][1], acc[mi][ni][1]);
                            acc[mi][ni][2] = fmaf(kv[mi][1], atap[mi][ni][2], acc[mi][ni][2]);
                            acc[mi][ni][3] = fmaf(kv[mi][1], atap[mi][ni][3], acc[mi][ni][3]);
                        }
                }
            }
            GBAR(barid);   // all warps done reading A before next ky build
        }

        // ---- epilogue ----
        if (!FINAL) {
            // direct NHWC float2 stores + fused instance-norm sums
            float2 biasv[4];
#pragma unroll
            for (int ni = 0; ni < 4; ++ni)
                biasv[ni] = *(const float2*)(sb + BIAS_OFF + (wn * 32 + ni * 8 + cp) * 4);
            float sv[8], sq2[8];
#pragma unroll
            for (int q = 0; q < 8; ++q) { sv[q] = 0.f; sq2[q] = 0.f; }
            const size_t rowb = ((((size_t)b * 256 + y) * 256 + x0) << 6);
#pragma unroll
            for (int mi = 0; mi < 2; ++mi) {
                int px = wm * 32 + mi * 16 + row4;
                float* p0 = out + rowb + ((size_t)px << 6);
                float* p1 = p0 + (8 << 6);
#pragma unroll
                for (int ni = 0; ni < 4; ++ni) {
                    int oc = wn * 32 + ni * 8 + cp;
                    float v0 = acc[mi][ni][0] + biasv[ni].x;
                    float v1 = acc[mi][ni][1] + biasv[ni].y;
                    float v2 = acc[mi][ni][2] + biasv[ni].x;
                    float v3 = acc[mi][ni][3] + biasv[ni].y;
                    *(float2*)(p0 + oc) = make_float2(v0, v1);
                    *(float2*)(p1 + oc) = make_float2(v2, v3);
                    sv[ni * 2 + 0] += v0 + v2;
                    sv[ni * 2 + 1] += v1 + v3;
                    sq2[ni * 2 + 0] = fmaf(v0, v0, fmaf(v2, v2, sq2[ni * 2 + 0]));
                    sq2[ni * 2 + 1] = fmaf(v1, v1, fmaf(v3, v3, sq2[ni * 2 + 1]));
                }
            }
#pragma unroll
            for (int off = 4; off < 32; off <<= 1)
#pragma unroll
                for (int q = 0; q < 8; ++q) {
                    sv[q]  += __shfl_xor_sync(0xffffffffu, sv[q],  off);
                    sq2[q] += __shfl_xor_sync(0xffffffffu, sq2[q], off);
                }
            if (lane < 4) {
#pragma unroll
                for (int ni = 0; ni < 4; ++ni) {
                    int oc = b * 64 + wn * 32 + ni * 8 + lane * 2;
                    atomicAdd(&sums[oc],     sv[ni * 2 + 0]);
                    atomicAdd(&sums[oc + 1], sv[ni * 2 + 1]);
                    atomicAdd(&sumsqs[oc],     sq2[ni * 2 + 0]);
                    atomicAdd(&sumsqs[oc + 1], sq2[ni * 2 + 1]);
                }
            }
        } else {
            // NCHW + bias + relu via two 64-px smem phases (A region overlay)
            float* epi = (float*)(sb + A_OFF + g * A_STRIDE);   // [64][66]
#pragma unroll
            for (int phase = 0; phase < 2; ++phase) {
                if ((wm >> 1) == phase) {
                    int pxl = (wm & 1) * 32 + row4;
#pragma unroll
                    for (int mi = 0; mi < 2; ++mi)
#pragma unroll
                        for (int ni = 0; ni < 4; ++ni) {
                            int oc = wn * 32 + ni * 8 + cp;
                            int pl = pxl + mi * 16;
                            *(float2*)&epi[pl * 66 + oc] =
                                make_float2(acc[mi][ni][0], acc[mi][ni][1]);
                            *(float2*)&epi[(pl + 8) * 66 + oc] =
                                make_float2(acc[mi][ni][2], acc[mi][ni][3]);
                        }
                }
                GBAR(barid);
                for (int i = tg; i < 4096; i += 256) {
                    int oc = i >> 6, px = i & 63;
                    float bv = *(const float*)(sb + BIAS_OFF + oc * 4);
                    float v = fmaxf(epi[px * 66 + oc] + bv, 0.f);
                    out[((size_t)(b * 64 + oc) << 16) + y * 256 + x0 + phase * 64 + px] = v;
                }
                GBAR(barid);
            }
        }
    }
}

// =======================================================================
// Aux kernels (NHWC)
// =======================================================================
__global__ void conv1x1_kernel(const float* __restrict__ x,
                               const float* __restrict__ w0,
                               const float* __restrict__ b0,
                               float* __restrict__ h)   // NHWC out
{
    __shared__ float sw[64], sbv[64];
    int tid = threadIdx.x;
    if (tid < 64) { sw[tid] = w0[tid]; sbv[tid] = b0[tid]; }
    __syncthreads();
    int b = blockIdx.x >> 8, y = blockIdx.x & 255;
    const float* xr = x + ((size_t)b << 16) + y * 256;
    float* ob = h + ((((size_t)b * 256 + y) * 256) << 6);
    int c = tid & 63;
    float wv = sw[c], bv = sbv[c];
    for (int i = 0; i < 64; ++i) {
        int px = i * 4 + (tid >> 6);
        ob[((size_t)px << 6) + c] = fmaf(wv, xr[px], bv);
    }
}

__global__ void finalize_stats_kernel(float* __restrict__ sums,
                                      float* __restrict__ sumsqs,
                                      float* __restrict__ meanv,
                                      float* __restrict__ rstdv)
{
    int bc = threadIdx.x;
    float m   = sums[bc]   * (1.0f / 65536.0f);
    float var = sumsqs[bc] * (1.0f / 65536.0f) - m * m;
    meanv[bc] = m;
    rstdv[bc] = rsqrtf(var + 1e-5f);
    sums[bc] = 0.f;
    sumsqs[bc] = 0.f;
}

__global__ void combine_kernel(float4* __restrict__ h,         // NHWC
                               const float4* __restrict__ t2,
                               const float* __restrict__ meanv,
                               const float* __restrict__ rstdv)
{
    size_t i = (size_t)blockIdx.x * 256 + threadIdx.x;   // 4,194,304 float4
    int c4 = (int)(i & 15);
    int b  = (int)(i >> 20);
    float4 m4 = ((const float4*)meanv)[(b << 4) + c4];
    float4 r4 = ((const float4*)rstdv)[(b << 4) + c4];
    float4 t = t2[i];
    float4 hv = h[i];
    hv.x = fmaxf(hv.x + (t.x - m4.x) * r4.x, 0.f);
    hv.y = fmaxf(hv.y + (t.y - m4.y) * r4.y, 0.f);
    hv.z = fmaxf(hv.z + (t.z - m4.z) * r4.z, 0.f);
    hv.w = fmaxf(hv.w + (t.w - m4.w) * r4.w, 0.f);
    h[i] = hv;
}

// =======================================================================
// launcher
// =======================================================================
extern "C" void kernel_launch(void* const* d_in, const int* in_sizes, int n_in,
                              void* d_out, int out_size)
{
    (void)in_sizes; (void)n_in; (void)out_size;
    const float* x  = (const float*)d_in[0];
    const float* w0 = (const float*)d_in[2];
    const float* b0 = (const float*)d_in[3];
    const float* wf = (const float*)d_in[4];
    const float* bf = (const float*)d_in[5];
    const float* wa[3] = {(const float*)d_in[6],  (const float*)d_in[10], (const float*)d_in[14]};
    const float* ba[3] = {(const float*)d_in[7],  (const float*)d_in[11], (const float*)d_in[15]};
    const float* wb[3] = {(const float*)d_in[8],  (const float*)d_in[12], (const float*)d_in[16]};
    const float* bb[3] = {(const float*)d_in[9],  (const float*)d_in[13], (const float*)d_in[17]};

    float *h, *t1, *t2, *mv, *rv, *sm, *sq;
    cudaGetSymbolAddress((void**)&h,  g_h);
    cudaGetSymbolAddress((void**)&t1, g_t1);
    cudaGetSymbolAddress((void**)&t2, g_t2);
    cudaGetSymbolAddress((void**)&mv, g_mean);
    cudaGetSymbolAddress((void**)&rv, g_rstd);
    cudaGetSymbolAddress((void**)&sm, g_sum);
    cudaGetSymbolAddress((void**)&sq, g_sumsq);

    cudaFuncSetAttribute(pac_mma_kernel<false, true,  false>,
                         cudaFuncAttributeMaxDynamicSharedMemorySize, DSMEM);
    cudaFuncSetAttribute(pac_mma_kernel<true,  true,  false>,
                         cudaFuncAttributeMaxDynamicSharedMemorySize, DSMEM);
    cudaFuncSetAttribute(pac_mma_kernel<false, false, true>,
                         cudaFuncAttributeMaxDynamicSharedMemorySize, DSMEM);

    conv1x1_kernel<<<1024, 256>>>(x, w0, b0, h);

    for (int r = 0; r < 3; ++r) {
        pac_mma_kernel<false, true, false><<<148, 512, DSMEM>>>(
            h, x, wa[r], ba[r], nullptr, nullptr, t1, sm, sq);
        finalize_stats_kernel<<<1, 256>>>(sm, sq, mv, rv);

        pac_mma_kernel<true, true, false><<<148, 512, DSMEM>>>(
            t1, x, wb[r], bb[r], mv, rv, t2, sm, sq);
        finalize_stats_kernel<<<1, 256>>>(sm, sq, mv, rv);

        combine_kernel<<<16384, 256>>>((float4*)h, (const float4*)t2, mv, rv);
    }

    pac_mma_kernel<false, false, true><<<148, 512, DSMEM>>>(
        h, x, wf, bf, nullptr, nullptr, (float*)d_out, sm, sq);
}

// round 10
// speedup vs baseline: 4.7161x; 1.0599x over previous
#include <cuda_runtime.h>
#include <cuda_bf16.h>
#include <cstdint>
#include <cstddef>

typedef unsigned long long u64;
typedef unsigned int u32;

// ---------------- device scratch (no cudaMalloc allowed) ----------------
// NHWC feature buffers [b][y][x][c], 4*256*256*64 floats each
__device__ float g_h [16777216];
__device__ float g_t1[16777216];
__device__ float g_t2[16777216];
__device__ __align__(16) float g_mean[256];
__device__ __align__(16) float g_rstd[256];
__device__ __align__(16) float g_sum[256];     // zero-init; finalize re-zeroes
__device__ __align__(16) float g_sumsq[256];

// ---------------- helpers ----------------
__device__ __forceinline__ u32 smem_u32(const void* p) {
    u32 a;
    asm("{ .reg .u64 t; cvta.to.shared.u64 t, %1; cvt.u32.u64 %0, t; }"
        : "=r"(a) : "l"(p));
    return a;
}
__device__ __forceinline__ u32 swz(u32 off) { return off ^ ((off >> 3) & 0x70); }
__device__ __forceinline__ int reflx(int i) { return i < 0 ? 1 : (i >= 256 ? 254 : i); }

__device__ __forceinline__ void ldsm4(u32* r, u32 addr) {
    asm volatile("ldmatrix.sync.aligned.m8n8.x4.shared.b16 {%0,%1,%2,%3}, [%4];"
        : "=r"(r[0]), "=r"(r[1]), "=r"(r[2]), "=r"(r[3]) : "r"(addr));
}
__device__ __forceinline__ void mma16816(float* d, const u32* a, const u32* b) {
    asm volatile(
        "mma.sync.aligned.m16n8k16.row.col.f32.bf16.bf16.f32 "
        "{%0,%1,%2,%3}, {%4,%5,%6,%7}, {%8,%9}, {%0,%1,%2,%3};"
        : "+f"(d[0]), "+f"(d[1]), "+f"(d[2]), "+f"(d[3])
        : "r"(a[0]), "r"(a[1]), "r"(a[2]), "r"(a[3]), "r"(b[0]), "r"(b[1]));
}
#define GBAR(id) asm volatile("bar.sync %0, 128;" :: "r"(id) : "memory")

// ---------------- smem layout (relative to 1024-aligned base) ----------------
// [0     : 256   ) bias (64 f32)
// [512   : 9728  ) s_k  float [4 groups][9][64]
// [10240 : 157696) W tiles: [tap][hi/lo][64 oc][128B row], swizzled (9*16384)
// [157696: 225280) A tiles: 4 groups x 16896 B (66 rows x 128B, hi then lo)
//                  (FINAL epilogue overlays the group's A region)
#define BIAS_OFF  0
#define K_OFF     512
#define W_OFF     10240
#define A_OFF     157696
#define A_STRIDE  16896
#define A_LO_REL  8448
#define DSMEM     (157696 + 4 * 16896 + 1024)

// =======================================================================
// PAC conv via mma.sync, shifted-ldmatrix implicit GEMM.
// bf16 hi/lo split (3 passes), fp32 accum; guide kernel applied in fp32 on
// per-tap register accumulators. 512 thr = 4 independent 4-warp tile groups
// (64-px tiles, per-group named barriers).
// in NHWC; out NHWC + fused stats (FINAL: NCHW + relu, no stats).
// =======================================================================
template <bool NORM_IN, bool USE_K, bool FINAL>
__global__ void __launch_bounds__(512, 1)
pac_mma_kernel(const float* __restrict__ in,
               const float* __restrict__ guide,
               const float* __restrict__ w,      // [64][64][3][3] fp32
               const float* __restrict__ bias,
               const float* __restrict__ meanv,
               const float* __restrict__ rstdv,
               float* __restrict__ out,
               float* __restrict__ sums,
               float* __restrict__ sumsqs)
{
    extern __shared__ __align__(16) unsigned char dyn[];
    u32 raw0  = smem_u32(dyn);
    u32 smem0 = (raw0 + 1023) & ~1023u;
    unsigned char* sb = dyn + (smem0 - raw0);

    const int tid  = threadIdx.x;
    const int warp = tid >> 5;
    const int lane = tid & 31;
    const int g    = warp >> 2;        // tile group 0..3
    const int wg   = warp & 3;         // warp within group
    const int tgl  = wg * 32 + lane;   // thread within group (0..127)
    const int wm   = wg >> 1;          // 0/1 : 32-px group
    const int wn   = wg & 1;           // 0/1 : 32-oc group
    const int barid = 1 + g;

    // ---- one-time: weights (hi/lo, swizzled rows) + bias ----
    for (int i = tid; i < 36864; i += 512) {
        int oc  = i / 576;
        int r   = i - oc * 576;
        int c   = r / 9;
        int tap = r - c * 9;
        float wv = w[i];
        __nv_bfloat16 hb = __float2bfloat16(wv);
        __nv_bfloat16 lb = __float2bfloat16(wv - __bfloat162float(hb));
        u32 off = swz((u32)(oc * 128 + c * 2));
        *(__nv_bfloat16*)(sb + W_OFF + tap * 16384 +        off) = hb;
        *(__nv_bfloat16*)(sb + W_OFF + tap * 16384 + 8192 + off) = lb;
    }
    if (tid < 64) *(float*)(sb + BIAS_OFF + tid * 4) = bias[tid];
    __syncthreads();

    float2 nm = make_float2(0.f, 0.f), nr = make_float2(1.f, 1.f);
    int cur_b = -1;

    const u32 aHi = smem0 + A_OFF + g * A_STRIDE;
    const u32 aLo = aHi + A_LO_REL;
    float* sk = (float*)(sb + K_OFF + g * 2304);
    const int cp   = (lane & 3) * 2;
    const int row4 = lane >> 2;

    // B-operand ldsm row offset (32 oc per warp via two x4 loads)
    const u32 bRowOff = (u32)((wn * 32 + ((lane >> 4) << 3) + (lane & 7)) * 128
                              + ((lane >> 3) & 1) * 16);

    for (int tile = blockIdx.x * 4 + g; tile < 4096; tile += gridDim.x * 4) {
        const int b   = tile >> 10;
        const int rem = tile & 1023;
        const int y   = rem >> 2;
        const int x0  = (rem & 3) << 6;
        int yy[3];
        yy[0] = (y == 0) ? 1 : y - 1;
        yy[1] = y;
        yy[2] = (y == 255) ? 254 : y + 1;

        if (NORM_IN && b != cur_b) {
            nm = *(const float2*)(meanv + b * 64 + 2 * lane);
            nr = *(const float2*)(rstdv + b * 64 + 2 * lane);
            cur_b = b;
        }

        if (USE_K) {
            // direct-LDG k build (guide rows L1-hot).
            // sk writes covered by the first build GBAR below.
            const float* gp  = guide + ((size_t)b << 16);
            const float* gc0 = gp + y * 256 + x0;
#pragma unroll
            for (int it = 0; it < 5; ++it) {
                int i = tgl + it * 128;
                if (i < 576) {
                    int t9 = i >> 6, px = i & 63;
                    float gs = gp[yy[t9 / 3] * 256 + reflx(x0 + px + (t9 % 3) - 1)];
                    float d  = gs - gc0[px];
                    sk[i] = __expf(-0.5f * d * d);
                }
            }
        }

        float acc[2][4][4];
#pragma unroll
        for (int mi = 0; mi < 2; ++mi)
#pragma unroll
            for (int ni = 0; ni < 4; ++ni)
#pragma unroll
                for (int q = 0; q < 4; ++q) acc[mi][ni][q] = 0.f;

        for (int ky = 0; ky < 3; ++ky) {
            // ---- build raw (normed) x tile for this ky: 66 rows hi/lo ----
            const float* rowbase =
                in + ((((size_t)b * 256 + yy[ky]) * 256) << 6) + 2 * lane;
            for (int r = wg; r < 66; r += 4) {
                int xg = x0 - 1 + r;
                xg = xg < 0 ? 1 : (xg > 255 ? 254 : xg);
                float2 v = *(const float2*)(rowbase + ((size_t)xg << 6));
                float p0 = v.x, p1 = v.y;
                if (NORM_IN) {
                    p0 = fmaxf((p0 - nm.x) * nr.x, 0.f);
                    p1 = fmaxf((p1 - nm.y) * nr.y, 0.f);
                }
                __nv_bfloat162 h2 = __float22bfloat162_rn(make_float2(p0, p1));
                float l0 = p0 - __bfloat162float(h2.x);
                float l1 = p1 - __bfloat162float(h2.y);
                __nv_bfloat162 lo2 = __float22bfloat162_rn(make_float2(l0, l1));
                u32 off = swz((u32)(r * 128 + lane * 4));
                *(u32*)(sb + (A_OFF + g * A_STRIDE) + off)            = *(u32*)&h2;
                *(u32*)(sb + (A_OFF + g * A_STRIDE) + A_LO_REL + off) = *(u32*)&lo2;
            }
            GBAR(barid);

#pragma unroll
            for (int kx = 0; kx < 3; ++kx) {
                const int t9 = ky * 3 + kx;
                const u32 wHi = smem0 + W_OFF + t9 * 16384;
                const u32 wLo = wHi + 8192;
                // shifted A row offsets (row = px + kx in 66-row tile)
                u32 arow[2];
#pragma unroll
                for (int mi = 0; mi < 2; ++mi)
                    arow[mi] = (u32)((wm * 32 + (lane & 15) + mi * 16 + kx) * 128
                                     + (lane >> 4) * 16);

                float atap[2][4][4];
                if (USE_K) {
#pragma unroll
                    for (int mi = 0; mi < 2; ++mi)
#pragma unroll
                        for (int ni = 0; ni < 4; ++ni)
#pragma unroll
                            for (int q = 0; q < 4; ++q) atap[mi][ni][q] = 0.f;
                }
#define DST(mi, ni) (USE_K ? atap[mi][ni] : acc[mi][ni])

                // per ks: 8 ldsm upfront, then 24 mma
#pragma unroll
                for (int ks = 0; ks < 4; ++ks) {
                    u32 afh[2][4], afl[2][4], bh[2][4], bl[2][4];
#pragma unroll
                    for (int mi = 0; mi < 2; ++mi) {
                        ldsm4(afh[mi], aHi + swz(arow[mi] + ks * 32));
                        ldsm4(afl[mi], aLo + swz(arow[mi] + ks * 32));
                    }
#pragma unroll
                    for (int p = 0; p < 2; ++p) {
                        ldsm4(bh[p], wHi + swz(bRowOff + p * 16 * 128 + ks * 32));
                        ldsm4(bl[p], wLo + swz(bRowOff + p * 16 * 128 + ks * 32));
                    }
#pragma unroll
                    for (int mi = 0; mi < 2; ++mi)
#pragma unroll
                        for (int ni = 0; ni < 4; ++ni) {
                            mma16816(DST(mi, ni), afh[mi], &bh[ni >> 1][(ni & 1) * 2]);
                            mma16816(DST(mi, ni), afl[mi], &bh[ni >> 1][(ni & 1) * 2]);
                            mma16816(DST(mi, ni), afh[mi], &bl[ni >> 1][(ni & 1) * 2]);
                        }
                }
#undef DST

                if (USE_K) {
                    float kv[2][2];
#pragma unroll
                    for (int mi = 0; mi < 2; ++mi) {
                        kv[mi][0] = sk[t9 * 64 + wm * 32 + mi * 16 + row4];
                        kv[mi][1] = sk[t9 * 64 + wm * 32 + mi * 16 + row4 + 8];
                    }
#pragma unroll
                    for (int mi = 0; mi < 2; ++mi)
#pragma unroll
                        for (int ni = 0; ni < 4; ++ni) {
                            acc[mi][ni][0] = fmaf(kv[mi][0], atap[mi][ni][0], acc[mi][ni][0]);
                            acc[mi][ni][1] = fmaf(kv[mi][0], atap[mi][ni][1], acc[mi][ni][1]);
                            acc[mi][ni][2] = fmaf(kv[mi][1], atap[mi][ni][2], acc[mi][ni][2]);
                            acc[mi][ni][3] = fmaf(kv[mi][1], atap[mi][ni][3], acc[mi][ni][3]);
                        }
                }
            }
            GBAR(barid);   // all group warps done reading A before next ky build
        }

        // ---- epilogue ----
        if (!FINAL) {
            // direct NHWC float2 stores + fused instance-norm sums
            float2 biasv[4];
#pragma unroll
            for (int ni = 0; ni < 4; ++ni)
                biasv[ni] = *(const float2*)(sb + BIAS_OFF + (wn * 32 + ni * 8 + cp) * 4);
            float sv[8], sq2[8];
#pragma unroll
            for (int q = 0; q < 8; ++q) { sv[q] = 0.f; sq2[q] = 0.f; }
            const size_t rowb = ((((size_t)b * 256 + y) * 256 + x0) << 6);
#pragma unroll
            for (int mi = 0; mi < 2; ++mi) {
                int px = wm * 32 + mi * 16 + row4;
                float* p0 = out + rowb + ((size_t)px << 6);
                float* p1 = p0 + (8 << 6);
#pragma unroll
                for (int ni = 0; ni < 4; ++ni) {
                    int oc = wn * 32 + ni * 8 + cp;
                    float v0 = acc[mi][ni][0] + biasv[ni].x;
                    float v1 = acc[mi][ni][1] + biasv[ni].y;
                    float v2 = acc[mi][ni][2] + biasv[ni].x;
                    float v3 = acc[mi][ni][3] + biasv[ni].y;
                    *(float2*)(p0 + oc) = make_float2(v0, v1);
                    *(float2*)(p1 + oc) = make_float2(v2, v3);
                    sv[ni * 2 + 0] += v0 + v2;
                    sv[ni * 2 + 1] += v1 + v3;
                    sq2[ni * 2 + 0] = fmaf(v0, v0, fmaf(v2, v2, sq2[ni * 2 + 0]));
                    sq2[ni * 2 + 1] = fmaf(v1, v1, fmaf(v3, v3, sq2[ni * 2 + 1]));
                }
            }
#pragma unroll
            for (int off = 4; off < 32; off <<= 1)
#pragma unroll
                for (int q = 0; q < 8; ++q) {
                    sv[q]  += __shfl_xor_sync(0xffffffffu, sv[q],  off);
                    sq2[q] += __shfl_xor_sync(0xffffffffu, sq2[q], off);
                }
            if (lane < 4) {
#pragma unroll
                for (int ni = 0; ni < 4; ++ni) {
                    int oc = b * 64 + wn * 32 + ni * 8 + lane * 2;
                    atomicAdd(&sums[oc],     sv[ni * 2 + 0]);
                    atomicAdd(&sums[oc + 1], sv[ni * 2 + 1]);
                    atomicAdd(&sumsqs[oc],     sq2[ni * 2 + 0]);
                    atomicAdd(&sumsqs[oc + 1], sq2[ni * 2 + 1]);
                }
            }
        } else {
            // NCHW + bias + relu via group A-region overlay [64][66]
            float* epi = (float*)(sb + A_OFF + g * A_STRIDE);
            {
                int pxl = wm * 32 + row4;
#pragma unroll
                for (int mi = 0; mi < 2; ++mi)
#pragma unroll
                    for (int ni = 0; ni < 4; ++ni) {
                        int oc = wn * 32 + ni * 8 + cp;
                        int pl = pxl + mi * 16;
                        *(float2*)&epi[pl * 66 + oc] =
                            make_float2(acc[mi][ni][0], acc[mi][ni][1]);
                        *(float2*)&epi[(pl + 8) * 66 + oc] =
                            make_float2(acc[mi][ni][2], acc[mi][ni][3]);
                    }
            }
            GBAR(barid);
            for (int i = tgl; i < 4096; i += 128) {
                int oc = i >> 6, px = i & 63;
                float bv = *(const float*)(sb + BIAS_OFF + oc * 4);
                float v = fmaxf(epi[px * 66 + oc] + bv, 0.f);
                out[((size_t)(b * 64 + oc) << 16) + y * 256 + x0 + px] = v;
            }
            GBAR(barid);   // epi region free before next tile's build
        }
    }
}

// =======================================================================
// Aux kernels (NHWC)
// =======================================================================
__global__ void conv1x1_kernel(const float* __restrict__ x,
                               const float* __restrict__ w0,
                               const float* __restrict__ b0,
                               float* __restrict__ h)   // NHWC out
{
    __shared__ float sw[64], sbv[64];
    int tid = threadIdx.x;
    if (tid < 64) { sw[tid] = w0[tid]; sbv[tid] = b0[tid]; }
    __syncthreads();
    int b = blockIdx.x >> 8, y = blockIdx.x & 255;
    const float* xr = x + ((size_t)b << 16) + y * 256;
    float* ob = h + ((((size_t)b * 256 + y) * 256) << 6);
    int c = tid & 63;
    float wv = sw[c], bv = sbv[c];
    for (int i = 0; i < 64; ++i) {
        int px = i * 4 + (tid >> 6);
        ob[((size_t)px << 6) + c] = fmaf(wv, xr[px], bv);
    }
}

__global__ void finalize_stats_kernel(float* __restrict__ sums,
                                      float* __restrict__ sumsqs,
                                      float* __restrict__ meanv,
                                      float* __restrict__ rstdv)
{
    int bc = threadIdx.x;
    float m   = sums[bc]   * (1.0f / 65536.0f);
    float var = sumsqs[bc] * (1.0f / 65536.0f) - m * m;
    meanv[bc] = m;
    rstdv[bc] = rsqrtf(var + 1e-5f);
    sums[bc] = 0.f;
    sumsqs[bc] = 0.f;
}

__global__ void combine_kernel(float4* __restrict__ h,         // NHWC
                               const float4* __restrict__ t2,
                               const float* __restrict__ meanv,
                               const float* __restrict__ rstdv)
{
    size_t i = (size_t)blockIdx.x * 256 + threadIdx.x;   // 4,194,304 float4
    int c4 = (int)(i & 15);
    int b  = (int)(i >> 20);
    float4 m4 = ((const float4*)meanv)[(b << 4) + c4];
    float4 r4 = ((const float4*)rstdv)[(b << 4) + c4];
    float4 t = t2[i];
    float4 hv = h[i];
    hv.x = fmaxf(hv.x + (t.x - m4.x) * r4.x, 0.f);
    hv.y = fmaxf(hv.y + (t.y - m4.y) * r4.y, 0.f);
    hv.z = fmaxf(hv.z + (t.z - m4.z) * r4.z, 0.f);
    hv.w = fmaxf(hv.w + (t.w - m4.w) * r4.w, 0.f);
    h[i] = hv;
}

// =======================================================================
// launcher
// =======================================================================
extern "C" void kernel_launch(void* const* d_in, const int* in_sizes, int n_in,
                              void* d_out, int out_size)
{
    (void)in_sizes; (void)n_in; (void)out_size;
    const float* x  = (const float*)d_in[0];
    const float* w0 = (const float*)d_in[2];
    const float* b0 = (const float*)d_in[3];
    const float* wf = (const float*)d_in[4];
    const float* bf = (const float*)d_in[5];
    const float* wa[3] = {(const float*)d_in[6],  (const float*)d_in[10], (const float*)d_in[14]};
    const float* ba[3] = {(const float*)d_in[7],  (const float*)d_in[11], (const float*)d_in[15]};
    const float* wb[3] = {(const float*)d_in[8],  (const float*)d_in[12], (const float*)d_in[16]};
    const float* bb[3] = {(const float*)d_in[9],  (const float*)d_in[13], (const float*)d_in[17]};

    float *h, *t1, *t2, *mv, *rv, *sm, *sq;
    cudaGetSymbolAddress((void**)&h,  g_h);
    cudaGetSymbolAddress((void**)&t1, g_t1);
    cudaGetSymbolAddress((void**)&t2, g_t2);
    cudaGetSymbolAddress((void**)&mv, g_mean);
    cudaGetSymbolAddress((void**)&rv, g_rstd);
    cudaGetSymbolAddress((void**)&sm, g_sum);
    cudaGetSymbolAddress((void**)&sq, g_sumsq);

    cudaFuncSetAttribute(pac_mma_kernel<false, true,  false>,
                         cudaFuncAttributeMaxDynamicSharedMemorySize, DSMEM);
    cudaFuncSetAttribute(pac_mma_kernel<true,  true,  false>,
                         cudaFuncAttributeMaxDynamicSharedMemorySize, DSMEM);
    cudaFuncSetAttribute(pac_mma_kernel<false, false, true>,
                         cudaFuncAttributeMaxDynamicSharedMemorySize, DSMEM);

    conv1x1_kernel<<<1024, 256>>>(x, w0, b0, h);

    for (int r = 0; r < 3; ++r) {
        pac_mma_kernel<false, true, false><<<148, 512, DSMEM>>>(
            h, x, wa[r], ba[r], nullptr, nullptr, t1, sm, sq);
        finalize_stats_kernel<<<1, 256>>>(sm, sq, mv, rv);

        pac_mma_kernel<true, true, false><<<148, 512, DSMEM>>>(
            t1, x, wb[r], bb[r], mv, rv, t2, sm, sq);
        finalize_stats_kernel<<<1, 256>>>(sm, sq, mv, rv);

        combine_kernel<<<16384, 256>>>((float4*)h, (const float4*)t2, mv, rv);
    }

    pac_mma_kernel<false, false, true><<<148, 512, DSMEM>>>(
        h, x, wf, bf, nullptr, nullptr, (float*)d_out, sm, sq);
}

// round 11
// speedup vs baseline: 5.2106x; 1.1048x over previous
#include <cuda_runtime.h>
#include <cuda_bf16.h>
#include <cstdint>
#include <cstddef>

typedef unsigned long long u64;
typedef unsigned int u32;

// ---------------- device scratch (no cudaMalloc allowed) ----------------
// NHWC feature buffers [b][y][x][c], 4*256*256*64 floats each
__device__ float g_h [16777216];
__device__ float g_t1[16777216];
__device__ float g_t2[16777216];
__device__ __align__(16) float g_mean[256];
__device__ __align__(16) float g_rstd[256];
__device__ __align__(16) float g_sum[256];     // zero-init; finalize re-zeroes
__device__ __align__(16) float g_sumsq[256];

// ---------------- helpers ----------------
__device__ __forceinline__ u32 smem_u32(const void* p) {
    u32 a;
    asm("{ .reg .u64 t; cvta.to.shared.u64 t, %1; cvt.u32.u64 %0, t; }"
        : "=r"(a) : "l"(p));
    return a;
}
__device__ __forceinline__ u32 swz(u32 off) { return off ^ ((off >> 3) & 0x70); }
__device__ __forceinline__ int reflx(int i) { return i < 0 ? 1 : (i >= 256 ? 254 : i); }

__device__ __forceinline__ void ldsm4(u32* r, u32 addr) {
    asm volatile("ldmatrix.sync.aligned.m8n8.x4.shared.b16 {%0,%1,%2,%3}, [%4];"
        : "=r"(r[0]), "=r"(r[1]), "=r"(r[2]), "=r"(r[3]) : "r"(addr));
}
__device__ __forceinline__ void mma16816(float* d, const u32* a, const u32* b) {
    asm volatile(
        "mma.sync.aligned.m16n8k16.row.col.f32.bf16.bf16.f32 "
        "{%0,%1,%2,%3}, {%4,%5,%6,%7}, {%8,%9}, {%0,%1,%2,%3};"
        : "+f"(d[0]), "+f"(d[1]), "+f"(d[2]), "+f"(d[3])
        : "r"(a[0]), "r"(a[1]), "r"(a[2]), "r"(a[3]), "r"(b[0]), "r"(b[1]));
}
#define GBAR(id) asm volatile("bar.sync %0, 128;" :: "r"(id) : "memory")

// ---------------- smem layout (relative to 1024-aligned base) ----------------
// [0     : 256   ) bias (64 f32)
// [512   : 9728  ) s_k  float [4 groups][9][64]: slot0 = k_8, slots1-8 = ratios
// [10240 : 157696) W tiles: [tap][hi/lo][64 oc][128B row], swizzled (9*16384)
// [157696: 225280) A tiles: 4 groups x 16896 B (66 rows x 128B, hi then lo)
//                  (FINAL epilogue overlays the group's A region)
#define BIAS_OFF  0
#define K_OFF     512
#define W_OFF     10240
#define A_OFF     157696
#define A_STRIDE  16896
#define A_LO_REL  8448
#define DSMEM     (157696 + 4 * 16896 + 1024)

// =======================================================================
// PAC conv via mma.sync, shifted-ldmatrix implicit GEMM.
// bf16 hi/lo split (3 passes), fp32 accum; guide kernel applied via fp32
// accumulator ratio-rescaling (acc kept in 1/k_t space, k_8 applied in
// epilogue). A-build LDGs prefetched to registers under the MMA phase.
// 512 thr = 4 independent 4-warp tile groups (64-px tiles, named barriers).
// in NHWC; out NHWC + fused stats (FINAL: NCHW + relu, no stats).
// =======================================================================
template <bool NORM_IN, bool USE_K, bool FINAL>
__global__ void __launch_bounds__(512, 1)
pac_mma_kernel(const float* __restrict__ in,
               const float* __restrict__ guide,
               const float* __restrict__ w,      // [64][64][3][3] fp32
               const float* __restrict__ bias,
               const float* __restrict__ meanv,
               const float* __restrict__ rstdv,
               float* __restrict__ out,
               float* __restrict__ sums,
               float* __restrict__ sumsqs)
{
    extern __shared__ __align__(16) unsigned char dyn[];
    u32 raw0  = smem_u32(dyn);
    u32 smem0 = (raw0 + 1023) & ~1023u;
    unsigned char* sb = dyn + (smem0 - raw0);

    const int tid  = threadIdx.x;
    const int warp = tid >> 5;
    const int lane = tid & 31;
    const int g    = warp >> 2;        // tile group 0..3
    const int wg   = warp & 3;         // warp within group
    const int tgl  = wg * 32 + lane;   // thread within group (0..127)
    const int wm   = wg >> 1;          // 0/1 : 32-px group
    const int wn   = wg & 1;           // 0/1 : 32-oc group
    const int barid = 1 + g;

    // ---- one-time: weights (hi/lo, swizzled rows) + bias ----
    for (int i = tid; i < 36864; i += 512) {
        int oc  = i / 576;
        int r   = i - oc * 576;
        int c   = r / 9;
        int tap = r - c * 9;
        float wv = w[i];
        __nv_bfloat16 hb = __float2bfloat16(wv);
        __nv_bfloat16 lb = __float2bfloat16(wv - __bfloat162float(hb));
        u32 off = swz((u32)(oc * 128 + c * 2));
        *(__nv_bfloat16*)(sb + W_OFF + tap * 16384 +        off) = hb;
        *(__nv_bfloat16*)(sb + W_OFF + tap * 16384 + 8192 + off) = lb;
    }
    if (tid < 64) *(float*)(sb + BIAS_OFF + tid * 4) = bias[tid];
    __syncthreads();

    float2 nm = make_float2(0.f, 0.f), nr = make_float2(1.f, 1.f);
    int cur_b = -1;

    const u32 aHi = smem0 + A_OFF + g * A_STRIDE;
    const u32 aLo = aHi + A_LO_REL;
    const u32 aBase = A_OFF + g * A_STRIDE;
    float* sk = (float*)(sb + K_OFF + g * 2304);
    const int cp   = (lane & 3) * 2;
    const int row4 = lane >> 2;

    // B-operand ldsm row offset (32 oc per warp via two x4 loads)
    const u32 bRowOff = (u32)((wn * 32 + ((lane >> 4) << 3) + (lane & 7)) * 128
                              + ((lane >> 3) & 1) * 16);

    for (int tile = blockIdx.x * 4 + g; tile < 4096; tile += gridDim.x * 4) {
        const int b   = tile >> 10;
        const int rem = tile & 1023;
        const int y   = rem >> 2;
        const int x0  = (rem & 3) << 6;
        int yy[3];
        yy[0] = (y == 0) ? 1 : y - 1;
        yy[1] = y;
        yy[2] = (y == 255) ? 254 : y + 1;

        if (NORM_IN && b != cur_b) {
            nm = *(const float2*)(meanv + b * 64 + 2 * lane);
            nr = *(const float2*)(rstdv + b * 64 + 2 * lane);
            cur_b = b;
        }

        if (USE_K && tgl < 64) {
            // per-px serial k chain -> ratios (slots 1-8) + k_8 (slot 0).
            // sk writes become visible at the first build GBAR below.
            const int px = tgl;
            const float* gp = guide + ((size_t)b << 16);
            float gc = gp[y * 256 + x0 + px];
            float kprev = 1.f;
#pragma unroll
            for (int t = 0; t < 9; ++t) {
                float gs = gp[yy[t / 3] * 256 + reflx(x0 + px + (t % 3) - 1)];
                float d  = gs - gc;
                float k  = fmaxf(__expf(-0.5f * d * d), 1e-30f);
                if (t > 0) sk[t * 64 + px] = __fdividef(kprev, k);
                kprev = k;
            }
            sk[px] = kprev;   // k_8
        }

        float acc[2][4][4];
#pragma unroll
        for (int mi = 0; mi < 2; ++mi)
#pragma unroll
            for (int ni = 0; ni < 4; ++ni)
#pragma unroll
                for (int q = 0; q < 4; ++q) acc[mi][ni][q] = 0.f;

        float k8v[2][2];

        // ---- prologue: prefetch ky=0 rows into registers ----
        float2 pf[17];
        {
            const float* rowbase =
                in + ((((size_t)b * 256 + yy[0]) * 256) << 6) + 2 * lane;
#pragma unroll
            for (int j = 0; j < 17; ++j) {
                int r = wg + 4 * j;
                if (r < 66) {
                    int xg = x0 - 1 + r;
                    xg = xg < 0 ? 1 : (xg > 255 ? 254 : xg);
                    pf[j] = *(const float2*)(rowbase + ((size_t)xg << 6));
                }
            }
        }

#pragma unroll
        for (int ky = 0; ky < 3; ++ky) {
            // ---- convert + store prefetched rows (hi/lo, swizzled) ----
#pragma unroll
            for (int j = 0; j < 17; ++j) {
                int r = wg + 4 * j;
                if (r < 66) {
                    float p0 = pf[j].x, p1 = pf[j].y;
                    if (NORM_IN) {
                        p0 = fmaxf((p0 - nm.x) * nr.x, 0.f);
                        p1 = fmaxf((p1 - nm.y) * nr.y, 0.f);
                    }
                    __nv_bfloat162 h2 = __float22bfloat162_rn(make_float2(p0, p1));
                    float l0 = p0 - __bfloat162float(h2.x);
                    float l1 = p1 - __bfloat162float(h2.y);
                    __nv_bfloat162 lo2 = __float22bfloat162_rn(make_float2(l0, l1));
                    u32 off = swz((u32)(r * 128 + lane * 4));
                    *(u32*)(sb + aBase + off)            = *(u32*)&h2;
                    *(u32*)(sb + aBase + A_LO_REL + off) = *(u32*)&lo2;
                }
            }
            GBAR(barid);

            // ---- prefetch next ky under the MMA phase ----
            if (ky < 2) {
                const float* rowbase =
                    in + ((((size_t)b * 256 + yy[ky + 1]) * 256) << 6) + 2 * lane;
#pragma unroll
                for (int j = 0; j < 17; ++j) {
                    int r = wg + 4 * j;
                    if (r < 66) {
                        int xg = x0 - 1 + r;
                        xg = xg < 0 ? 1 : (xg > 255 ? 254 : xg);
                        pf[j] = *(const float2*)(rowbase + ((size_t)xg << 6));
                    }
                }
            }

#pragma unroll
            for (int kx = 0; kx < 3; ++kx) {
                const int t9 = ky * 3 + kx;
                const u32 wHi = smem0 + W_OFF + t9 * 16384;
                const u32 wLo = wHi + 8192;
                // shifted A row offsets (row = px + kx in 66-row tile)
                u32 arow[2];
#pragma unroll
                for (int mi = 0; mi < 2; ++mi)
                    arow[mi] = (u32)((wm * 32 + (lane & 15) + mi * 16 + kx) * 128
                                     + (lane >> 4) * 16);

                // rescale acc into 1/k_t space
                if (USE_K && t9 > 0) {
                    float rv[2][2];
#pragma unroll
                    for (int mi = 0; mi < 2; ++mi) {
                        rv[mi][0] = sk[t9 * 64 + wm * 32 + mi * 16 + row4];
                        rv[mi][1] = sk[t9 * 64 + wm * 32 + mi * 16 + row4 + 8];
                    }
#pragma unroll
                    for (int mi = 0; mi < 2; ++mi)
#pragma unroll
                        for (int ni = 0; ni < 4; ++ni) {
                            acc[mi][ni][0] *= rv[mi][0];
                            acc[mi][ni][1] *= rv[mi][0];
                            acc[mi][ni][2] *= rv[mi][1];
                            acc[mi][ni][3] *= rv[mi][1];
                        }
                }

                // per ks: 8 ldsm upfront, then 24 mma directly into acc
#pragma unroll
                for (int ks = 0; ks < 4; ++ks) {
                    u32 afh[2][4], afl[2][4], bh[2][4], bl[2][4];
#pragma unroll
                    for (int mi = 0; mi < 2; ++mi) {
                        ldsm4(afh[mi], aHi + swz(arow[mi] + ks * 32));
                        ldsm4(afl[mi], aLo + swz(arow[mi] + ks * 32));
                    }
#pragma unroll
                    for (int p = 0; p < 2; ++p) {
                        ldsm4(bh[p], wHi + swz(bRowOff + p * 16 * 128 + ks * 32));
                        ldsm4(bl[p], wLo + swz(bRowOff + p * 16 * 128 + ks * 32));
                    }
#pragma unroll
                    for (int mi = 0; mi < 2; ++mi)
#pragma unroll
                        for (int ni = 0; ni < 4; ++ni) {
                            mma16816(acc[mi][ni], afh[mi], &bh[ni >> 1][(ni & 1) * 2]);
                            mma16816(acc[mi][ni], afl[mi], &bh[ni >> 1][(ni & 1) * 2]);
                            mma16816(acc[mi][ni], afh[mi], &bl[ni >> 1][(ni & 1) * 2]);
                        }
                }
            }
            // load k_8 before the closing barrier (next tile's s_k build
            // by warps 0-1 happens after this barrier -> no WAR race)
            if (ky == 2 && USE_K) {
#pragma unroll
                for (int mi = 0; mi < 2; ++mi) {
                    k8v[mi][0] = sk[wm * 32 + mi * 16 + row4];
                    k8v[mi][1] = sk[wm * 32 + mi * 16 + row4 + 8];
                }
            }
            GBAR(barid);   // all group warps done reading A before next ky build
        }

        // ---- epilogue ----
        if (!FINAL) {
            // direct NHWC float2 stores + fused instance-norm sums
            float2 biasv[4];
#pragma unroll
            for (int ni = 0; ni < 4; ++ni)
                biasv[ni] = *(const float2*)(sb + BIAS_OFF + (wn * 32 + ni * 8 + cp) * 4);
            float sv[8], sq2[8];
#pragma unroll
            for (int q = 0; q < 8; ++q) { sv[q] = 0.f; sq2[q] = 0.f; }
            const size_t rowb = ((((size_t)b * 256 + y) * 256 + x0) << 6);
#pragma unroll
            for (int mi = 0; mi < 2; ++mi) {
                int px = wm * 32 + mi * 16 + row4;
                float* p0 = out + rowb + ((size_t)px << 6);
                float* p1 = p0 + (8 << 6);
#pragma unroll
                for (int ni = 0; ni < 4; ++ni) {
                    int oc = wn * 32 + ni * 8 + cp;
                    float v0, v1, v2, v3;
                    if (USE_K) {
                        v0 = fmaf(acc[mi][ni][0], k8v[mi][0], biasv[ni].x);
                        v1 = fmaf(acc[mi][ni][1], k8v[mi][0], biasv[ni].y);
                        v2 = fmaf(acc[mi][ni][2], k8v[mi][1], biasv[ni].x);
                        v3 = fmaf(acc[mi][ni][3], k8v[mi][1], biasv[ni].y);
                    } else {
                        v0 = acc[mi][ni][0] + biasv[ni].x;
                        v1 = acc[mi][ni][1] + biasv[ni].y;
                        v2 = acc[mi][ni][2] + biasv[ni].x;
                        v3 = acc[mi][ni][3] + biasv[ni].y;
                    }
                    *(float2*)(p0 + oc) = make_float2(v0, v1);
                    *(float2*)(p1 + oc) = make_float2(v2, v3);
                    sv[ni * 2 + 0] += v0 + v2;
                    sv[ni * 2 + 1] += v1 + v3;
                    sq2[ni * 2 + 0] = fmaf(v0, v0, fmaf(v2, v2, sq2[ni * 2 + 0]));
                    sq2[ni * 2 + 1] = fmaf(v1, v1, fmaf(v3, v3, sq2[ni * 2 + 1]));
                }
            }
#pragma unroll
            for (int off = 4; off < 32; off <<= 1)
#pragma unroll
                for (int q = 0; q < 8; ++q) {
                    sv[q]  += __shfl_xor_sync(0xffffffffu, sv[q],  off);
                    sq2[q] += __shfl_xor_sync(0xffffffffu, sq2[q], off);
                }
            if (lane < 4) {
#pragma unroll
                for (int ni = 0; ni < 4; ++ni) {
                    int oc = b * 64 + wn * 32 + ni * 8 + lane * 2;
                    atomicAdd(&sums[oc],     sv[ni * 2 + 0]);
                    atomicAdd(&sums[oc + 1], sv[ni * 2 + 1]);
                    atomicAdd(&sumsqs[oc],     sq2[ni * 2 + 0]);
                    atomicAdd(&sumsqs[oc + 1], sq2[ni * 2 + 1]);
                }
            }
        } else {
            // NCHW + bias + relu via group A-region overlay [64][66]
            float* epi = (float*)(sb + aBase);
            {
                int pxl = wm * 32 + row4;
#pragma unroll
                for (int mi = 0; mi < 2; ++mi)
#pragma unroll
                    for (int ni = 0; ni < 4; ++ni) {
                        int oc = wn * 32 + ni * 8 + cp;
                        int pl = pxl + mi * 16;
                        *(float2*)&epi[pl * 66 + oc] =
                            make_float2(acc[mi][ni][0], acc[mi][ni][1]);
                        *(float2*)&epi[(pl + 8) * 66 + oc] =
                            make_float2(acc[mi][ni][2], acc[mi][ni][3]);
                    }
            }
            GBAR(barid);
            for (int i = tgl; i < 4096; i += 128) {
                int oc = i >> 6, px = i & 63;
                float bv = *(const float*)(sb + BIAS_OFF + oc * 4);
                float v = fmaxf(epi[px * 66 + oc] + bv, 0.f);
                out[((size_t)(b * 64 + oc) << 16) + y * 256 + x0 + px] = v;
            }
            GBAR(barid);   // epi region free before next tile's build
        }
    }
}

// =======================================================================
// Aux kernels (NHWC)
// =======================================================================
__global__ void conv1x1_kernel(const float* __restrict__ x,
                               const float* __restrict__ w0,
                               const float* __restrict__ b0,
                               float* __restrict__ h)   // NHWC out
{
    __shared__ float sw[64], sbv[64];
    int tid = threadIdx.x;
    if (tid < 64) { sw[tid] = w0[tid]; sbv[tid] = b0[tid]; }
    __syncthreads();
    int b = blockIdx.x >> 8, y = blockIdx.x & 255;
    const float* xr = x + ((size_t)b << 16) + y * 256;
    float* ob = h + ((((size_t)b * 256 + y) * 256) << 6);
    int c = tid & 63;
    float wv = sw[c], bv = sbv[c];
    for (int i = 0; i < 64; ++i) {
        int px = i * 4 + (tid >> 6);
        ob[((size_t)px << 6) + c] = fmaf(wv, xr[px], bv);
    }
}

__global__ void finalize_stats_kernel(float* __restrict__ sums,
                                      float* __restrict__ sumsqs,
                                      float* __restrict__ meanv,
                                      float* __restrict__ rstdv)
{
    int bc = threadIdx.x;
    float m   = sums[bc]   * (1.0f / 65536.0f);
    float var = sumsqs[bc] * (1.0f / 65536.0f) - m * m;
    meanv[bc] = m;
    rstdv[bc] = rsqrtf(var + 1e-5f);
    sums[bc] = 0.f;
    sumsqs[bc] = 0.f;
}

__global__ void combine_kernel(float4* __restrict__ h,         // NHWC
                               const float4* __restrict__ t2,
                               const float* __restrict__ meanv,
                               const float* __restrict__ rstdv)
{
    size_t i = (size_t)blockIdx.x * 256 + threadIdx.x;   // 4,194,304 float4
    int c4 = (int)(i & 15);
    int b  = (int)(i >> 20);
    float4 m4 = ((const float4*)meanv)[(b << 4) + c4];
    float4 r4 = ((const float4*)rstdv)[(b << 4) + c4];
    float4 t = t2[i];
    float4 hv = h[i];
    hv.x = fmaxf(hv.x + (t.x - m4.x) * r4.x, 0.f);
    hv.y = fmaxf(hv.y + (t.y - m4.y) * r4.y, 0.f);
    hv.z = fmaxf(hv.z + (t.z - m4.z) * r4.z, 0.f);
    hv.w = fmaxf(hv.w + (t.w - m4.w) * r4.w, 0.f);
    h[i] = hv;
}

// =======================================================================
// launcher
// =======================================================================
extern "C" void kernel_launch(void* const* d_in, const int* in_sizes, int n_in,
                              void* d_out, int out_size)
{
    (void)in_sizes; (void)n_in; (void)out_size;
    const float* x  = (const float*)d_in[0];
    const float* w0 = (const float*)d_in[2];
    const float* b0 = (const float*)d_in[3];
    const float* wf = (const float*)d_in[4];
    const float* bf = (const float*)d_in[5];
    const float* wa[3] = {(const float*)d_in[6],  (const float*)d_in[10], (const float*)d_in[14]};
    const float* ba[3] = {(const float*)d_in[7],  (const float*)d_in[11], (const float*)d_in[15]};
    const float* wb[3] = {(const float*)d_in[8],  (const float*)d_in[12], (const float*)d_in[16]};
    const float* bb[3] = {(const float*)d_in[9],  (const float*)d_in[13], (const float*)d_in[17]};

    float *h, *t1, *t2, *mv, *rv, *sm, *sq;
    cudaGetSymbolAddress((void**)&h,  g_h);
    cudaGetSymbolAddress((void**)&t1, g_t1);
    cudaGetSymbolAddress((void**)&t2, g_t2);
    cudaGetSymbolAddress((void**)&mv, g_mean);
    cudaGetSymbolAddress((void**)&rv, g_rstd);
    cudaGetSymbolAddress((void**)&sm, g_sum);
    cudaGetSymbolAddress((void**)&sq, g_sumsq);

    cudaFuncSetAttribute(pac_mma_kernel<false, true,  false>,
                         cudaFuncAttributeMaxDynamicSharedMemorySize, DSMEM);
    cudaFuncSetAttribute(pac_mma_kernel<true,  true,  false>,
                         cudaFuncAttributeMaxDynamicSharedMemorySize, DSMEM);
    cudaFuncSetAttribute(pac_mma_kernel<false, false, true>,
                         cudaFuncAttributeMaxDynamicSharedMemorySize, DSMEM);

    conv1x1_kernel<<<1024, 256>>>(x, w0, b0, h);

    for (int r = 0; r < 3; ++r) {
        pac_mma_kernel<false, true, false><<<148, 512, DSMEM>>>(
            h, x, wa[r], ba[r], nullptr, nullptr, t1, sm, sq);
        finalize_stats_kernel<<<1, 256>>>(sm, sq, mv, rv);

        pac_mma_kernel<true, true, false><<<148, 512, DSMEM>>>(
            t1, x, wb[r], bb[r], mv, rv, t2, sm, sq);
        finalize_stats_kernel<<<1, 256>>>(sm, sq, mv, rv);

        combine_kernel<<<16384, 256>>>((float4*)h, (const float4*)t2, mv, rv);
    }

    pac_mma_kernel<false, false, true><<<148, 512, DSMEM>>>(
        h, x, wf, bf, nullptr, nullptr, (float*)d_out, sm, sq);
}

// round 12
// speedup vs baseline: 5.2863x; 1.0145x over previous
#include <cuda_runtime.h>
#include <cuda_bf16.h>
#include <cstdint>
#include <cstddef>

typedef unsigned long long u64;
typedef unsigned int u32;

// ---------------- device scratch (no cudaMalloc allowed) ----------------
// NHWC feature buffers [b][y][x][c], 4*256*256*64 floats each
__device__ float g_h [16777216];
__device__ float g_t1[16777216];
__device__ float g_t2[16777216];
__device__ __align__(16) float g_mean[256];
__device__ __align__(16) float g_rstd[256];
__device__ __align__(16) float g_sum[256];     // zero-init; finalize re-zeroes
__device__ __align__(16) float g_sumsq[256];

// ---------------- helpers ----------------
__device__ __forceinline__ u32 smem_u32(const void* p) {
    u32 a;
    asm("{ .reg .u64 t; cvta.to.shared.u64 t, %1; cvt.u32.u64 %0, t; }"
        : "=r"(a) : "l"(p));
    return a;
}
__device__ __forceinline__ u32 swz(u32 off) { return off ^ ((off >> 3) & 0x70); }
__device__ __forceinline__ int reflx(int i) { return i < 0 ? 1 : (i >= 256 ? 254 : i); }

__device__ __forceinline__ void ldsm4(u32* r, u32 addr) {
    asm volatile("ldmatrix.sync.aligned.m8n8.x4.shared.b16 {%0,%1,%2,%3}, [%4];"
        : "=r"(r[0]), "=r"(r[1]), "=r"(r[2]), "=r"(r[3]) : "r"(addr));
}
__device__ __forceinline__ void mma16816(float* d, const u32* a, const u32* b) {
    asm volatile(
        "mma.sync.aligned.m16n8k16.row.col.f32.bf16.bf16.f32 "
        "{%0,%1,%2,%3}, {%4,%5,%6,%7}, {%8,%9}, {%0,%1,%2,%3};"
        : "+f"(d[0]), "+f"(d[1]), "+f"(d[2]), "+f"(d[3])
        : "r"(a[0]), "r"(a[1]), "r"(a[2]), "r"(a[3]), "r"(b[0]), "r"(b[1]));
}
#define GBAR(id) asm volatile("bar.sync %0, 64;" :: "r"(id) : "memory")

// ---------------- smem layout (relative to 1024-aligned base) ----------------
// [0     : 256   ) bias (64 f32)
// [512   : 9728  ) s_k  float [8 groups][9][32]: slot0 = k_8, slots1-8 = ratios
// [10240 : 157696) W tiles: [tap][hi/lo][64 oc][128B row], swizzled (9*16384)
// [157696: 227328) A tiles: 8 groups x 8704 B (34 rows x 128B, hi then lo)
//                  (FINAL epilogue overlays the group's A region: [32][66] f32)
#define BIAS_OFF  0
#define K_OFF     512
#define W_OFF     10240
#define A_OFF     157696
#define A_STRIDE  8704
#define A_LO_REL  4352
#define DSMEM     (227328 + 1024)

// =======================================================================
// PAC conv via mma.sync, shifted-ldmatrix implicit GEMM.
// bf16 hi/lo split (3 passes), fp32 accum; guide kernel applied via fp32
// accumulator ratio-rescaling (acc kept in 1/k_t space, k_8 in epilogue).
// A-build LDGs prefetched to registers under the MMA phase.
// 512 thr = 8 independent 2-warp tile groups (32-px tiles, 64-thread
// named barriers): 8 async phase streams per SM.
// in NHWC; out NHWC + fused stats (FINAL: NCHW + relu, no stats).
// =======================================================================
template <bool NORM_IN, bool USE_K, bool FINAL>
__global__ void __launch_bounds__(512, 1)
pac_mma_kernel(const float* __restrict__ in,
               const float* __restrict__ guide,
               const float* __restrict__ w,      // [64][64][3][3] fp32
               const float* __restrict__ bias,
               const float* __restrict__ meanv,
               const float* __restrict__ rstdv,
               float* __restrict__ out,
               float* __restrict__ sums,
               float* __restrict__ sumsqs)
{
    extern __shared__ __align__(16) unsigned char dyn[];
    u32 raw0  = smem_u32(dyn);
    u32 smem0 = (raw0 + 1023) & ~1023u;
    unsigned char* sb = dyn + (smem0 - raw0);

    const int tid  = threadIdx.x;
    const int warp = tid >> 5;
    const int lane = tid & 31;
    const int g    = warp >> 1;        // tile group 0..7
    const int wn   = warp & 1;         // 0/1 : 32-oc half within group
    const int tgl  = wn * 32 + lane;   // thread within group (0..63)
    const int barid = 1 + g;           // named barrier ids 1..8

    // ---- one-time: weights (hi/lo, swizzled rows) + bias ----
    for (int i = tid; i < 36864; i += 512) {
        int oc  = i / 576;
        int r   = i - oc * 576;
        int c   = r / 9;
        int tap = r - c * 9;
        float wv = w[i];
        __nv_bfloat16 hb = __float2bfloat16(wv);
        __nv_bfloat16 lb = __float2bfloat16(wv - __bfloat162float(hb));
        u32 off = swz((u32)(oc * 128 + c * 2));
        *(__nv_bfloat16*)(sb + W_OFF + tap * 16384 +        off) = hb;
        *(__nv_bfloat16*)(sb + W_OFF + tap * 16384 + 8192 + off) = lb;
    }
    if (tid < 64) *(float*)(sb + BIAS_OFF + tid * 4) = bias[tid];
    __syncthreads();

    float2 nm = make_float2(0.f, 0.f), nr = make_float2(1.f, 1.f);
    int cur_b = -1;

    const u32 aBase = A_OFF + g * A_STRIDE;
    const u32 aHi = smem0 + aBase;
    const u32 aLo = aHi + A_LO_REL;
    float* sk = (float*)(sb + K_OFF + g * 1152);
    const int cp   = (lane & 3) * 2;
    const int row4 = lane >> 2;

    // B-operand ldsm row offset (32 oc per warp via two x4 loads)
    const u32 bRowOff = (u32)((wn * 32 + ((lane >> 4) << 3) + (lane & 7)) * 128
                              + ((lane >> 3) & 1) * 16);

    for (int tile = blockIdx.x * 8 + g; tile < 8192; tile += gridDim.x * 8) {
        const int b   = tile >> 11;
        const int rem = tile & 2047;
        const int y   = rem >> 3;
        const int x0  = (rem & 7) << 5;
        int yy[3];
        yy[0] = (y == 0) ? 1 : y - 1;
        yy[1] = y;
        yy[2] = (y == 255) ? 254 : y + 1;

        if (NORM_IN && b != cur_b) {
            nm = *(const float2*)(meanv + b * 64 + 2 * lane);
            nr = *(const float2*)(rstdv + b * 64 + 2 * lane);
            cur_b = b;
        }

        if (USE_K && tgl < 32) {
            // per-px serial k chain -> ratios (slots 1-8) + k_8 (slot 0).
            // sk writes become visible at the first build GBAR below.
            const int px = tgl;
            const float* gp = guide + ((size_t)b << 16);
            float gc = gp[y * 256 + x0 + px];
            float kprev = 1.f;
#pragma unroll
            for (int t = 0; t < 9; ++t) {
                float gs = gp[yy[t / 3] * 256 + reflx(x0 + px + (t % 3) - 1)];
                float d  = gs - gc;
                float k  = fmaxf(__expf(-0.5f * d * d), 1e-30f);
                if (t > 0) sk[t * 32 + px] = __fdividef(kprev, k);
                kprev = k;
            }
            sk[px] = kprev;   // k_8
        }

        float acc[2][4][4];
#pragma unroll
        for (int mi = 0; mi < 2; ++mi)
#pragma unroll
            for (int ni = 0; ni < 4; ++ni)
#pragma unroll
                for (int q = 0; q < 4; ++q) acc[mi][ni][q] = 0.f;

        float k8v[2][2];

        // ---- prologue: prefetch ky=0 rows into registers (17 per warp) ----
        float2 pf[17];
        {
            const float* rowbase =
                in + ((((size_t)b * 256 + yy[0]) * 256) << 6) + 2 * lane;
#pragma unroll
            for (int j = 0; j < 17; ++j) {
                int r = wn + 2 * j;       // rows 0..33
                int xg = x0 - 1 + r;
                xg = xg < 0 ? 1 : (xg > 255 ? 254 : xg);
                pf[j] = *(const float2*)(rowbase + ((size_t)xg << 6));
            }
        }

#pragma unroll
        for (int ky = 0; ky < 3; ++ky) {
            // ---- convert + store prefetched rows (hi/lo, swizzled) ----
#pragma unroll
            for (int j = 0; j < 17; ++j) {
                int r = wn + 2 * j;
                float p0 = pf[j].x, p1 = pf[j].y;
                if (NORM_IN) {
                    p0 = fmaxf((p0 - nm.x) * nr.x, 0.f);
                    p1 = fmaxf((p1 - nm.y) * nr.y, 0.f);
                }
                __nv_bfloat162 h2 = __float22bfloat162_rn(make_float2(p0, p1));
                float l0 = p0 - __bfloat162float(h2.x);
                float l1 = p1 - __bfloat162float(h2.y);
                __nv_bfloat162 lo2 = __float22bfloat162_rn(make_float2(l0, l1));
                u32 off = swz((u32)(r * 128 + lane * 4));
                *(u32*)(sb + aBase + off)            = *(u32*)&h2;
                *(u32*)(sb + aBase + A_LO_REL + off) = *(u32*)&lo2;
            }
            GBAR(barid);

            // ---- prefetch next ky under the MMA phase ----
            if (ky < 2) {
                const float* rowbase =
                    in + ((((size_t)b * 256 + yy[ky + 1]) * 256) << 6) + 2 * lane;
#pragma unroll
                for (int j = 0; j < 17; ++j) {
                    int r = wn + 2 * j;
                    int xg = x0 - 1 + r;
                    xg = xg < 0 ? 1 : (xg > 255 ? 254 : xg);
                    pf[j] = *(const float2*)(rowbase + ((size_t)xg << 6));
                }
            }

#pragma unroll
            for (int kx = 0; kx < 3; ++kx) {
                const int t9 = ky * 3 + kx;
                const u32 wHi = smem0 + W_OFF + t9 * 16384;
                const u32 wLo = wHi + 8192;
                // shifted A row offsets (row = px + kx in 34-row tile)
                u32 arow[2];
#pragma unroll
                for (int mi = 0; mi < 2; ++mi)
                    arow[mi] = (u32)(((lane & 15) + mi * 16 + kx) * 128
                                     + (lane >> 4) * 16);

                // rescale acc into 1/k_t space
                if (USE_K && t9 > 0) {
                    float rv[2][2];
#pragma unroll
                    for (int mi = 0; mi < 2; ++mi) {
                        rv[mi][0] = sk[t9 * 32 + mi * 16 + row4];
                        rv[mi][1] = sk[t9 * 32 + mi * 16 + row4 + 8];
                    }
#pragma unroll
                    for (int mi = 0; mi < 2; ++mi)
#pragma unroll
                        for (int ni = 0; ni < 4; ++ni) {
                            acc[mi][ni][0] *= rv[mi][0];
                            acc[mi][ni][1] *= rv[mi][0];
                            acc[mi][ni][2] *= rv[mi][1];
                            acc[mi][ni][3] *= rv[mi][1];
                        }
                }

                // per ks: 8 ldsm upfront, then 24 mma directly into acc
#pragma unroll
                for (int ks = 0; ks < 4; ++ks) {
                    u32 afh[2][4], afl[2][4], bh[2][4], bl[2][4];
#pragma unroll
                    for (int mi = 0; mi < 2; ++mi) {
                        ldsm4(afh[mi], aHi + swz(arow[mi] + ks * 32));
                        ldsm4(afl[mi], aLo + swz(arow[mi] + ks * 32));
                    }
#pragma unroll
                    for (int p = 0; p < 2; ++p) {
                        ldsm4(bh[p], wHi + swz(bRowOff + p * 16 * 128 + ks * 32));
                        ldsm4(bl[p], wLo + swz(bRowOff + p * 16 * 128 + ks * 32));
                    }
#pragma unroll
                    for (int mi = 0; mi < 2; ++mi)
#pragma unroll
                        for (int ni = 0; ni < 4; ++ni) {
                            mma16816(acc[mi][ni], afh[mi], &bh[ni >> 1][(ni & 1) * 2]);
                            mma16816(acc[mi][ni], afl[mi], &bh[ni >> 1][(ni & 1) * 2]);
                            mma16816(acc[mi][ni], afh[mi], &bl[ni >> 1][(ni & 1) * 2]);
                        }
                }
            }
            // load k_8 before the closing barrier (next tile's s_k build
            // happens after this barrier -> no WAR race)
            if (ky == 2 && USE_K) {
#pragma unroll
                for (int mi = 0; mi < 2; ++mi) {
                    k8v[mi][0] = sk[mi * 16 + row4];
                    k8v[mi][1] = sk[mi * 16 + row4 + 8];
                }
            }
            GBAR(barid);   // both group warps done reading A before next build
        }

        // ---- epilogue ----
        if (!FINAL) {
            // direct NHWC float2 stores + fused instance-norm sums
            float2 biasv[4];
#pragma unroll
            for (int ni = 0; ni < 4; ++ni)
                biasv[ni] = *(const float2*)(sb + BIAS_OFF + (wn * 32 + ni * 8 + cp) * 4);
            float sv[8], sq2[8];
#pragma unroll
            for (int q = 0; q < 8; ++q) { sv[q] = 0.f; sq2[q] = 0.f; }
            const size_t rowb = ((((size_t)b * 256 + y) * 256 + x0) << 6);
#pragma unroll
            for (int mi = 0; mi < 2; ++mi) {
                int px = mi * 16 + row4;
                float* p0 = out + rowb + ((size_t)px << 6);
                float* p1 = p0 + (8 << 6);
#pragma unroll
                for (int ni = 0; ni < 4; ++ni) {
                    int oc = wn * 32 + ni * 8 + cp;
                    float v0, v1, v2, v3;
                    if (USE_K) {
                        v0 = fmaf(acc[mi][ni][0], k8v[mi][0], biasv[ni].x);
                        v1 = fmaf(acc[mi][ni][1], k8v[mi][0], biasv[ni].y);
                        v2 = fmaf(acc[mi][ni][2], k8v[mi][1], biasv[ni].x);
                        v3 = fmaf(acc[mi][ni][3], k8v[mi][1], biasv[ni].y);
                    } else {
                        v0 = acc[mi][ni][0] + biasv[ni].x;
                        v1 = acc[mi][ni][1] + biasv[ni].y;
                        v2 = acc[mi][ni][2] + biasv[ni].x;
                        v3 = acc[mi][ni][3] + biasv[ni].y;
                    }
                    *(float2*)(p0 + oc) = make_float2(v0, v1);
                    *(float2*)(p1 + oc) = make_float2(v2, v3);
                    sv[ni * 2 + 0] += v0 + v2;
                    sv[ni * 2 + 1] += v1 + v3;
                    sq2[ni * 2 + 0] = fmaf(v0, v0, fmaf(v2, v2, sq2[ni * 2 + 0]));
                    sq2[ni * 2 + 1] = fmaf(v1, v1, fmaf(v3, v3, sq2[ni * 2 + 1]));
                }
            }
#pragma unroll
            for (int off = 4; off < 32; off <<= 1)
#pragma unroll
                for (int q = 0; q < 8; ++q) {
                    sv[q]  += __shfl_xor_sync(0xffffffffu, sv[q],  off);
                    sq2[q] += __shfl_xor_sync(0xffffffffu, sq2[q], off);
                }
            if (lane < 4) {
#pragma unroll
                for (int ni = 0; ni < 4; ++ni) {
                    int oc = b * 64 + wn * 32 + ni * 8 + lane * 2;
                    atomicAdd(&sums[oc],     sv[ni * 2 + 0]);
                    atomicAdd(&sums[oc + 1], sv[ni * 2 + 1]);
                    atomicAdd(&sumsqs[oc],     sq2[ni * 2 + 0]);
                    atomicAdd(&sumsqs[oc + 1], sq2[ni * 2 + 1]);
                }
            }
        } else {
            // NCHW + bias + relu via group A-region overlay [32][66]
            float* epi = (float*)(sb + aBase);
            {
#pragma unroll
                for (int mi = 0; mi < 2; ++mi)
#pragma unroll
                    for (int ni = 0; ni < 4; ++ni) {
                        int oc = wn * 32 + ni * 8 + cp;
                        int pl = mi * 16 + row4;
                        *(float2*)&epi[pl * 66 + oc] =
                            make_float2(acc[mi][ni][0], acc[mi][ni][1]);
                        *(float2*)&epi[(pl + 8) * 66 + oc] =
                            make_float2(acc[mi][ni][2], acc[mi][ni][3]);
                    }
            }
            GBAR(barid);
            for (int i = tgl; i < 2048; i += 64) {
                int oc = i >> 5, px = i & 31;
                float bv = *(const float*)(sb + BIAS_OFF + oc * 4);
                float v = fmaxf(epi[px * 66 + oc] + bv, 0.f);
                out[((size_t)(b * 64 + oc) << 16) + y * 256 + x0 + px] = v;
            }
            GBAR(barid);   // epi region free before next tile's build
        }
    }
}

// =======================================================================
// Aux kernels (NHWC)
// =======================================================================
__global__ void conv1x1_kernel(const float* __restrict__ x,
                               const float* __restrict__ w0,
                               const float* __restrict__ b0,
                               float* __restrict__ h)   // NHWC out
{
    __shared__ float sw[64], sbv[64];
    int tid = threadIdx.x;
    if (tid < 64) { sw[tid] = w0[tid]; sbv[tid] = b0[tid]; }
    __syncthreads();
    int b = blockIdx.x >> 8, y = blockIdx.x & 255;
    const float* xr = x + ((size_t)b << 16) + y * 256;
    float* ob = h + ((((size_t)b * 256 + y) * 256) << 6);
    int c = tid & 63;
    float wv = sw[c], bv = sbv[c];
    for (int i = 0; i < 64; ++i) {
        int px = i * 4 + (tid >> 6);
        ob[((size_t)px << 6) + c] = fmaf(wv, xr[px], bv);
    }
}

__global__ void finalize_stats_kernel(float* __restrict__ sums,
                                      float* __restrict__ sumsqs,
                                      float* __restrict__ meanv,
                                      float* __restrict__ rstdv)
{
    int bc = threadIdx.x;
    float m   = sums[bc]   * (1.0f / 65536.0f);
    float var = sumsqs[bc] * (1.0f / 65536.0f) - m * m;
    meanv[bc] = m;
    rstdv[bc] = rsqrtf(var + 1e-5f);
    sums[bc] = 0.f;
    sumsqs[bc] = 0.f;
}

__global__ void combine_kernel(float4* __restrict__ h,         // NHWC
                               const float4* __restrict__ t2,
                               const float* __restrict__ meanv,
                               const float* __restrict__ rstdv)
{
    size_t i = (size_t)blockIdx.x * 256 + threadIdx.x;   // 4,194,304 float4
    int c4 = (int)(i & 15);
    int b  = (int)(i >> 20);
    float4 m4 = ((const float4*)meanv)[(b << 4) + c4];
    float4 r4 = ((const float4*)rstdv)[(b << 4) + c4];
    float4 t = t2[i];
    float4 hv = h[i];
    hv.x = fmaxf(hv.x + (t.x - m4.x) * r4.x, 0.f);
    hv.y = fmaxf(hv.y + (t.y - m4.y) * r4.y, 0.f);
    hv.z = fmaxf(hv.z + (t.z - m4.z) * r4.z, 0.f);
    hv.w = fmaxf(hv.w + (t.w - m4.w) * r4.w, 0.f);
    h[i] = hv;
}

// =======================================================================
// launcher
// =======================================================================
extern "C" void kernel_launch(void* const* d_in, const int* in_sizes, int n_in,
                              void* d_out, int out_size)
{
    (void)in_sizes; (void)n_in; (void)out_size;
    const float* x  = (const float*)d_in[0];
    const float* w0 = (const float*)d_in[2];
    const float* b0 = (const float*)d_in[3];
    const float* wf = (const float*)d_in[4];
    const float* bf = (const float*)d_in[5];
    const float* wa[3] = {(const float*)d_in[6],  (const float*)d_in[10], (const float*)d_in[14]};
    const float* ba[3] = {(const float*)d_in[7],  (const float*)d_in[11], (const float*)d_in[15]};
    const float* wb[3] = {(const float*)d_in[8],  (const float*)d_in[12], (const float*)d_in[16]};
    const float* bb[3] = {(const float*)d_in[9],  (const float*)d_in[13], (const float*)d_in[17]};

    float *h, *t1, *t2, *mv, *rv, *sm, *sq;
    cudaGetSymbolAddress((void**)&h,  g_h);
    cudaGetSymbolAddress((void**)&t1, g_t1);
    cudaGetSymbolAddress((void**)&t2, g_t2);
    cudaGetSymbolAddress((void**)&mv, g_mean);
    cudaGetSymbolAddress((void**)&rv, g_rstd);
    cudaGetSymbolAddress((void**)&sm, g_sum);
    cudaGetSymbolAddress((void**)&sq, g_sumsq);

    cudaFuncSetAttribute(pac_mma_kernel<false, true,  false>,
                         cudaFuncAttributeMaxDynamicSharedMemorySize, DSMEM);
    cudaFuncSetAttribute(pac_mma_kernel<true,  true,  false>,
                         cudaFuncAttributeMaxDynamicSharedMemorySize, DSMEM);
    cudaFuncSetAttribute(pac_mma_kernel<false, false, true>,
                         cudaFuncAttributeMaxDynamicSharedMemorySize, DSMEM);

    conv1x1_kernel<<<1024, 256>>>(x, w0, b0, h);

    for (int r = 0; r < 3; ++r) {
        pac_mma_kernel<false, true, false><<<148, 512, DSMEM>>>(
            h, x, wa[r], ba[r], nullptr, nullptr, t1, sm, sq);
        finalize_stats_kernel<<<1, 256>>>(sm, sq, mv, rv);

        pac_mma_kernel<true, true, false><<<148, 512, DSMEM>>>(
            t1, x, wb[r], bb[r], mv, rv, t2, sm, sq);
        finalize_stats_kernel<<<1, 256>>>(sm, sq, mv, rv);

        combine_kernel<<<16384, 256>>>((float4*)h, (const float4*)t2, mv, rv);
    }

    pac_mma_kernel<false, false, true><<<148, 512, DSMEM>>>(
        h, x, wf, bf, nullptr, nullptr, (float*)d_out, sm, sq);
}